// round 15
// baseline (speedup 1.0000x reference)
#include <cuda_runtime.h>
#include <cuda_bf16.h>
#include <cuda_fp16.h>
#include <cstdint>
#include <cstddef>

// ---------------- problem constants ----------------
#define BB   16
#define DIN  1024
#define TT   1024
#define KK   8192
#define DCB  256
#define NTOK (BB * TT)          // 16384

// ---------------- output layout (tuple flattened, f32) ----------------
static constexpr size_t OFF_ZQ     = 0;
static constexpr size_t SZ_ZQ      = (size_t)BB * DIN * TT;
static constexpr size_t OFF_IDX    = OFF_ZQ + SZ_ZQ;
static constexpr size_t OFF_COMMIT = OFF_IDX + NTOK;
static constexpr size_t OFF_CBL    = OFF_COMMIT + BB;
static constexpr size_t OFF_DIST   = OFF_CBL + BB;
static constexpr size_t SZ_DIST    = (size_t)NTOK * KK;
static constexpr size_t OFF_PERP   = OFF_DIST + SZ_DIST;
static constexpr size_t OFF_ACT    = OFF_PERP + 1;

// ---------------- scratch (device globals) ----------------
__device__ float g_cbn   [KK * DCB];        // normalized codebook, row-major (refine)
__device__ float g_colsq [KK];              // ||cb_n||^2
__device__ float g_cbsq  [KK];              // ||cb||^2 raw
__device__ float g_cbinv [KK];              // 1/max(||cb||,eps)
__device__ float g_ze    [BB * DCB * TT];
__device__ float g_inv   [NTOK];
__device__ float g_rowsq [NTOK];            // ||enc_n||^2
__device__ float g_rowsq_raw[NTOK];         // ||z_e||^2 raw
__device__ float g_lossn [NTOK];
__device__ int   g_idx   [NTOK];
__device__ int   g_counts[KK];
__device__ float g_proj  [KK * DIN];

// split operands (16B aligned for cp.async)
__device__ __align__(16) __nv_bfloat16 g_a_hi[(size_t)NTOK * DCB];   // enc_n rounded (bf16)
__device__ __align__(16) __nv_bfloat16 g_a_lo[(size_t)NTOK * DCB];   // enc_n residual (refine reconstruct)
__device__ __align__(16) __nv_bfloat16 g_b_hi[(size_t)KK * DCB];     // cb_n rounded (bf16)
__device__ __align__(16) __nv_bfloat16 g_cb_hi[(size_t)KK * DCB];    // raw cb split (bf16)
__device__ __align__(16) __nv_bfloat16 g_cb_lo[(size_t)KK * DCB];
__device__ __align__(16) __nv_bfloat16 g_wo_hi[(size_t)DIN * DCB];   // w_out split (bf16)
__device__ __align__(16) __nv_bfloat16 g_wo_lo[(size_t)DIN * DCB];
// fp16 split operands for z_e GEMM
__device__ __align__(16) __half g_wi_hi[(size_t)DCB * DIN];          // w_in split [c][k]
__device__ __align__(16) __half g_wi_lo[(size_t)DCB * DIN];
__device__ __align__(16) __half g_z_hi[(size_t)NTOK * DIN];          // z transposed [b][t][k]
__device__ __align__(16) __half g_z_lo[(size_t)NTOK * DIN];
// per-(token, 64-code tile) packed min (key<<32 | code), tile = k/64
__device__ unsigned long long g_tilemin[(size_t)NTOK * 128];

// ---------------- helpers ----------------
__device__ __forceinline__ uint32_t smem_u32(const void* p) {
    uint32_t a;
    asm("{ .reg .u64 t; cvta.to.shared.u64 t, %1; cvt.u32.u64 %0, t; }" : "=r"(a) : "l"(p));
    return a;
}
__device__ __forceinline__ void ldsm_x4(uint32_t* r, uint32_t a) {
    asm volatile("ldmatrix.sync.aligned.m8n8.x4.shared.b16 {%0,%1,%2,%3}, [%4];"
        : "=r"(r[0]), "=r"(r[1]), "=r"(r[2]), "=r"(r[3]) : "r"(a));
}
__device__ __forceinline__ void mma_bf16(float* d, const uint32_t* a, const uint32_t* b) {
    asm volatile("mma.sync.aligned.m16n8k16.row.col.f32.bf16.bf16.f32 "
        "{%0,%1,%2,%3}, {%4,%5,%6,%7}, {%8,%9}, {%0,%1,%2,%3};"
        : "+f"(d[0]), "+f"(d[1]), "+f"(d[2]), "+f"(d[3])
        : "r"(a[0]), "r"(a[1]), "r"(a[2]), "r"(a[3]), "r"(b[0]), "r"(b[1]));
}
__device__ __forceinline__ void mma_f16(float* d, const uint32_t* a, const uint32_t* b) {
    asm volatile("mma.sync.aligned.m16n8k16.row.col.f32.f16.f16.f32 "
        "{%0,%1,%2,%3}, {%4,%5,%6,%7}, {%8,%9}, {%0,%1,%2,%3};"
        : "+f"(d[0]), "+f"(d[1]), "+f"(d[2]), "+f"(d[3])
        : "r"(a[0]), "r"(a[1]), "r"(a[2]), "r"(a[3]), "r"(b[0]), "r"(b[1]));
}
#define CP_ASYNC16(dst, src) \
    asm volatile("cp.async.cg.shared.global [%0], [%1], 16;" :: "r"(dst), "l"(src) : "memory")
#define CP_COMMIT() asm volatile("cp.async.commit_group;" ::: "memory")
#define CP_WAIT1()  asm volatile("cp.async.wait_group 1;" ::: "memory")
#define CP_WAIT0()  asm volatile("cp.async.wait_group 0;" ::: "memory")

__device__ __forceinline__ unsigned fkey(float f) {
    unsigned u = __float_as_uint(f);
    return (u & 0x80000000u) ? ~u : (u | 0x80000000u);
}
__device__ __forceinline__ float funkey(unsigned k) {
    unsigned u = (k & 0x80000000u) ? (k ^ 0x80000000u) : ~k;
    return __uint_as_float(u);
}

// ---------------- prep A: w_in weight-norm -> fp16 split, row-major -------
__global__ void k_prep_win(const float* __restrict__ in_v, const float* __restrict__ in_g)
{
    int r   = blockIdx.x;                // 256 blocks
    int tid = threadIdx.x;
    const float* row = in_v + (size_t)r * DIN;
    float v4[4];
    float s = 0.f;
    #pragma unroll
    for (int i = 0; i < 4; i++) { v4[i] = row[tid * 4 + i]; s += v4[i] * v4[i]; }
    __shared__ float sm[256];
    sm[tid] = s; __syncthreads();
    #pragma unroll
    for (int off = 128; off; off >>= 1) {
        if (tid < off) sm[tid] += sm[tid + off];
        __syncthreads();
    }
    float scale = in_g[r] / sqrtf(sm[0]);
    __half2 h2a, h2b, l2a, l2b;
    float w0 = v4[0] * scale, w1 = v4[1] * scale, w2 = v4[2] * scale, w3 = v4[3] * scale;
    h2a = __floats2half2_rn(w0, w1);
    h2b = __floats2half2_rn(w2, w3);
    l2a = __floats2half2_rn(w0 - __half2float(h2a.x), w1 - __half2float(h2a.y));
    l2b = __floats2half2_rn(w2 - __half2float(h2b.x), w3 - __half2float(h2b.y));
    *(uint2*)(g_wi_hi + (size_t)r * DIN + tid * 4) =
        make_uint2(*(uint32_t*)&h2a, *(uint32_t*)&h2b);
    *(uint2*)(g_wi_lo + (size_t)r * DIN + tid * 4) =
        make_uint2(*(uint32_t*)&l2a, *(uint32_t*)&l2b);
}

// ---------------- z transpose + fp16 split:  [b][k][t] -> [b][t][k] -------
__global__ __launch_bounds__(256)
void k_zsplit(const float* __restrict__ z)
{
    __shared__ float tile[256][33];
    int k0 = blockIdx.x * 256;
    int t0 = blockIdx.y * 32;
    int b  = blockIdx.z;
    int tid = threadIdx.x;

    const float* zb = z + (size_t)b * DIN * TT + (size_t)k0 * TT + t0;
    #pragma unroll
    for (int i = 0; i < 32; i++) {
        int idx = tid + i * 256;
        int c = idx >> 5, t = idx & 31;
        tile[c][t] = zb[(size_t)c * TT + t];
    }
    __syncthreads();

    int j    = tid >> 3;               // token 0..31
    int part = tid & 7;                // 32-k slice
    uint32_t hw[16], lw[16];
    #pragma unroll
    for (int i = 0; i < 16; i++) {
        float v0 = tile[part * 32 + 2 * i][j];
        float v1 = tile[part * 32 + 2 * i + 1][j];
        __half2 h2 = __floats2half2_rn(v0, v1);
        __half2 l2 = __floats2half2_rn(v0 - __half2float(h2.x), v1 - __half2float(h2.y));
        hw[i] = *(uint32_t*)&h2;
        lw[i] = *(uint32_t*)&l2;
    }
    size_t base = ((size_t)b * TT + t0 + j) * DIN + k0 + part * 32;
    uint4* zh = (uint4*)(g_z_hi + base);
    uint4* zl = (uint4*)(g_z_lo + base);
    #pragma unroll
    for (int i = 0; i < 4; i++) {
        zh[i] = make_uint4(hw[4*i], hw[4*i+1], hw[4*i+2], hw[4*i+3]);
        zl[i] = make_uint4(lw[4*i], lw[4*i+1], lw[4*i+2], lw[4*i+3]);
    }
}

// ---------------- prep B: w_out + codebook norms & splits (stream 2) --------
__global__ void k_prep_cbwo(const float* __restrict__ out_v, const float* __restrict__ out_g,
                            const float* __restrict__ cb)
{
    int blk = blockIdx.x;
    int tid = threadIdx.x;
    __shared__ float sm[256];

    if (blk < 1024) {                                   // w_out: 1024 rows x 256
        int r = blk;
        const float* row = out_v + (size_t)r * DCB;
        float v = row[tid];
        sm[tid] = v * v; __syncthreads();
        #pragma unroll
        for (int off = 128; off; off >>= 1) {
            if (tid < off) sm[tid] += sm[tid + off];
            __syncthreads();
        }
        float scale = out_g[r] / sqrtf(sm[0]);
        float w = v * scale;
        __nv_bfloat16 hi = __float2bfloat16_rn(w);
        g_wo_hi[(size_t)r * DCB + tid] = hi;
        g_wo_lo[(size_t)r * DCB + tid] = __float2bfloat16_rn(w - __bfloat162float(hi));
    } else {                                            // codebook: 8192 rows x 256
        int r = blk - 1024;
        const float* row = cb + (size_t)r * DCB;
        float v = row[tid];
        sm[tid] = v * v; __syncthreads();
        #pragma unroll
        for (int off = 128; off; off >>= 1) {
            if (tid < off) sm[tid] += sm[tid + off];
            __syncthreads();
        }
        float sumsq = sm[0];
        float inv = 1.f / fmaxf(sqrtf(sumsq), 1e-12f);
        if (tid == 0) {
            g_colsq[r] = sumsq * inv * inv;
            g_cbsq[r]  = sumsq;
            g_cbinv[r] = inv;
            g_counts[r] = 0;
        }
        float vn = v * inv;
        g_cbn[(size_t)r * DCB + tid] = vn;
        g_b_hi[(size_t)r * DCB + tid] = __float2bfloat16_rn(vn);
        __nv_bfloat16 rh = __float2bfloat16_rn(v);
        g_cb_hi[(size_t)r * DCB + tid] = rh;
        g_cb_lo[(size_t)r * DCB + tid] = __float2bfloat16_rn(v - __bfloat162float(rh));
    }
}

// ---------------- per-token norms + bf16 split (coalesced) ----------------
__global__ __launch_bounds__(256)
void k_toknorm()
{
    __shared__ float tile[256][33];
    int blk = blockIdx.x;
    int b   = blk >> 5;
    int t0  = (blk & 31) << 5;
    int tid = threadIdx.x;

    const float* zb = g_ze + (size_t)b * DCB * TT + t0;
    #pragma unroll
    for (int i = 0; i < 32; i++) {
        int idx = tid + i * 256;
        int c = idx >> 5, t = idx & 31;
        tile[c][t] = zb[(size_t)c * TT + t];
    }
    __syncthreads();

    int j    = tid >> 3;
    int part = tid & 7;
    float s = 0.f;
    #pragma unroll
    for (int i = 0; i < 32; i++) {
        float v = tile[part * 32 + i][j];
        s += v * v;
    }
    s += __shfl_xor_sync(0xFFFFFFFFu, s, 4);
    s += __shfl_xor_sync(0xFFFFFFFFu, s, 2);
    s += __shfl_xor_sync(0xFFFFFFFFu, s, 1);
    float inv = 1.f / fmaxf(sqrtf(s), 1e-12f);

    int n = b * TT + t0 + j;
    if (part == 0) {
        g_inv[n] = inv;
        g_rowsq[n] = s * inv * inv;
        g_rowsq_raw[n] = s;
    }

    uint32_t hw[16], lw[16];
    #pragma unroll
    for (int i = 0; i < 16; i++) {
        float v0 = tile[part * 32 + 2 * i][j] * inv;
        float v1 = tile[part * 32 + 2 * i + 1][j] * inv;
        __nv_bfloat162 h2 = __floats2bfloat162_rn(v0, v1);
        float l0 = v0 - __bfloat162float(h2.x);
        float l1 = v1 - __bfloat162float(h2.y);
        __nv_bfloat162 l2 = __floats2bfloat162_rn(l0, l1);
        hw[i] = *(uint32_t*)&h2;
        lw[i] = *(uint32_t*)&l2;
    }
    uint4* ah = (uint4*)(g_a_hi + (size_t)n * DCB + part * 32);
    uint4* al = (uint4*)(g_a_lo + (size_t)n * DCB + part * 32);
    #pragma unroll
    for (int i = 0; i < 4; i++) {
        ah[i] = make_uint4(hw[4*i], hw[4*i+1], hw[4*i+2], hw[4*i+3]);
        al[i] = make_uint4(lw[4*i], lw[4*i+1], lw[4*i+2], lw[4*i+3]);
    }
}

// ---------------- HMMA GEMM tiles ----------------
static constexpr int ROWB      = 80;
static constexpr int MAT_BYTES = 128 * ROWB;          // 10240
static constexpr int STAGE2    = 2 * MAT_BYTES;       // dist: Ahi, Bhi (single pass)
static constexpr int STAGE4    = 4 * MAT_BYTES;       // 3-pass: Ahi, Alo, Bhi, Blo
static constexpr int COLSQ_OFF = 3 * STAGE2;          // 61440
static constexpr int SMEM_DIST = COLSQ_OFF + 128 * 4; // 61952
static constexpr int SMEM_P4   = 2 * STAGE4;          // 81920

// dist loader: 2 matrices (Ahi, Bhi), K stride 256
__device__ __forceinline__ void load_chunk2(uint32_t sbase, int stage, int kc,
                                            int m0, int n0, int tid)
{
    uint32_t st = sbase + stage * STAGE2;
    #pragma unroll
    for (int i = 0; i < 4; i++) {
        int lin = tid + i * 256;            // 0..1023
        int mat = lin >> 9;                 // 0..1
        int r   = (lin >> 2) & 127;
        int c   = lin & 3;
        uint32_t dst = st + mat * MAT_BYTES + (uint32_t)(r * ROWB + c * 16);
        size_t off = ((size_t)((mat == 0 ? m0 : n0) + r) * DCB + kc * 32) * 2 + c * 16;
        const char* src = (mat == 0) ? ((const char*)g_a_hi + off)
                                     : ((const char*)g_b_hi + off);
        CP_ASYNC16(dst, src);
    }
    CP_COMMIT();
}

__global__ __launch_bounds__(256, 2)
void k_dist(float* __restrict__ dout, int moff)
{
    extern __shared__ __align__(16) char smem_raw[];
    uint32_t sbase = smem_u32(smem_raw);
    float* colsq_s = (float*)(smem_raw + COLSQ_OFF);

    int tid  = threadIdx.x;
    int wid  = tid >> 5;
    int lane = tid & 31;
    int wm   = wid >> 1;
    int wn   = wid & 1;
    int n0   = blockIdx.x * 128;
    int m0   = moff + blockIdx.y * 128;

    if (tid < 128) colsq_s[tid] = g_colsq[n0 + tid];

    float acc[2][8][4];
    #pragma unroll
    for (int mt = 0; mt < 2; mt++)
        #pragma unroll
        for (int nt = 0; nt < 8; nt++)
            #pragma unroll
            for (int j = 0; j < 4; j++) acc[mt][nt][j] = 0.f;

    load_chunk2(sbase, 0, 0, m0, n0, tid);
    load_chunk2(sbase, 1, 1, m0, n0, tid);

    int arow  = wm * 32 + (lane & 15);
    int acolh = (lane >> 4) * 16;
    int brow  = wn * 64 + ((lane >> 4) << 3) + (lane & 7);
    int bcolh = ((lane >> 3) & 1) * 16;

    int stage = 0;
    for (int kc = 0; kc < 8; kc++) {
        if (kc < 7) { CP_WAIT1(); } else { CP_WAIT0(); }
        __syncthreads();
        if (kc + 2 < 8) {
            int nstage = stage + 2; if (nstage >= 3) nstage -= 3;
            load_chunk2(sbase, nstage, kc + 2, m0, n0, tid);
        }

        uint32_t sa_hi = sbase + stage * STAGE2;
        uint32_t sb_hi = sa_hi + MAT_BYTES;

        #pragma unroll
        for (int s = 0; s < 2; s++) {
            int acol = s * 32 + acolh;
            uint32_t Ahf[2][4];
            ldsm_x4(Ahf[0], sa_hi + (uint32_t)(arow * ROWB + acol));
            ldsm_x4(Ahf[1], sa_hi + (uint32_t)((arow + 16) * ROWB + acol));
            int bcol = s * 32 + bcolh;
            #pragma unroll
            for (int np = 0; np < 4; np++) {
                uint32_t Bhf[4];
                uint32_t ba = (uint32_t)((brow + np * 16) * ROWB + bcol);
                ldsm_x4(Bhf, sb_hi + ba);
                #pragma unroll
                for (int mt = 0; mt < 2; mt++) {
                    mma_bf16(acc[mt][2 * np],     Ahf[mt], Bhf);
                    mma_bf16(acc[mt][2 * np + 1], Ahf[mt], Bhf + 2);
                }
            }
        }
        stage = (stage + 1 == 3) ? 0 : stage + 1;
    }

    int q  = lane >> 2;
    int qq = lane & 3;
    int tileg = blockIdx.x * 2 + wn;
    #pragma unroll
    for (int mt = 0; mt < 2; mt++) {
        int RB = m0 + wm * 32 + mt * 16;
        #pragma unroll
        for (int h = 0; h < 2; h++) {
            int row = RB + h * 8 + q;
            float rsq = g_rowsq[row];
            float* dw = dout + OFF_DIST + (size_t)row * KK + n0;
            unsigned bkey = 0xFFFFFFFFu, bcode = 0;
            #pragma unroll
            for (int nt = 0; nt < 8; nt++) {
                int c0 = wn * 64 + nt * 8 + qq * 2;
                float d0 = rsq + colsq_s[c0]     - 2.f * acc[mt][nt][h * 2 + 0];
                float d1 = rsq + colsq_s[c0 + 1] - 2.f * acc[mt][nt][h * 2 + 1];
                *(float2*)(dw + c0) = make_float2(d0, d1);
                unsigned k0 = fkey(d0), k1 = fkey(d1);
                if (k0 < bkey) { bkey = k0; bcode = (unsigned)(n0 + c0); }
                if (k1 < bkey) { bkey = k1; bcode = (unsigned)(n0 + c0 + 1); }
            }
            unsigned long long p = ((unsigned long long)bkey << 32) | bcode;
            unsigned long long o;
            o = __shfl_xor_sync(0xFFFFFFFFu, p, 1); if (o < p) p = o;
            o = __shfl_xor_sync(0xFFFFFFFFu, p, 2); if (o < p) p = o;
            if (qq == 0) g_tilemin[(size_t)row * 128 + tileg] = p;
        }
    }
}

// ---------------- generic 4-matrix 3-pass HMMA mainloop ----------------
template<int KDIM>
__device__ __forceinline__ void load_chunk4T(uint32_t sbase, int stage, int kc,
                                             int m0, int n0, int tid,
                                             const void* Ah, const void* Al,
                                             const void* Bh, const void* Bl)
{
    uint32_t st = sbase + stage * STAGE4;
    #pragma unroll
    for (int i = 0; i < 8; i++) {
        int lin = tid + i * 256;
        int mat = lin >> 9;
        int r   = (lin >> 2) & 127;
        int c   = lin & 3;
        uint32_t dst = st + mat * MAT_BYTES + (uint32_t)(r * ROWB + c * 16);
        size_t off = ((size_t)((mat < 2 ? m0 : n0) + r) * KDIM + kc * 32) * 2 + c * 16;
        const char* src;
        if      (mat == 0) src = (const char*)Ah + off;
        else if (mat == 1) src = (const char*)Al + off;
        else if (mat == 2) src = (const char*)Bh + off;
        else               src = (const char*)Bl + off;
        CP_ASYNC16(dst, src);
    }
    CP_COMMIT();
}

template<int KDIM, bool HALF>
__device__ __forceinline__ void hmma4_loop(uint32_t sbase, int m0, int n0, int tid,
                                           const void* Ah, const void* Al,
                                           const void* Bh, const void* Bl,
                                           float acc[2][8][4])
{
    int wid  = tid >> 5;
    int lane = tid & 31;
    int wm   = wid >> 1;
    int wn   = wid & 1;

    load_chunk4T<KDIM>(sbase, 0, 0, m0, n0, tid, Ah, Al, Bh, Bl);

    int arow  = wm * 32 + (lane & 15);
    int acolh = (lane >> 4) * 16;
    int brow  = wn * 64 + ((lane >> 4) << 3) + (lane & 7);
    int bcolh = ((lane >> 3) & 1) * 16;

    constexpr int NCH = KDIM / 32;
    for (int kc = 0; kc < NCH; kc++) {
        int st = kc & 1;
        if (kc < NCH - 1) load_chunk4T<KDIM>(sbase, st ^ 1, kc + 1, m0, n0, tid, Ah, Al, Bh, Bl);
        if (kc < NCH - 1) { CP_WAIT1(); } else { CP_WAIT0(); }
        __syncthreads();

        uint32_t sa_hi = sbase + st * STAGE4;
        uint32_t sa_lo = sa_hi + MAT_BYTES;
        uint32_t sb_hi = sa_hi + 2 * MAT_BYTES;
        uint32_t sb_lo = sa_hi + 3 * MAT_BYTES;

        #pragma unroll
        for (int s = 0; s < 2; s++) {
            int acol = s * 32 + acolh;
            uint32_t Ahf[2][4], Alf[2][4];
            ldsm_x4(Ahf[0], sa_hi + (uint32_t)(arow * ROWB + acol));
            ldsm_x4(Ahf[1], sa_hi + (uint32_t)((arow + 16) * ROWB + acol));
            ldsm_x4(Alf[0], sa_lo + (uint32_t)(arow * ROWB + acol));
            ldsm_x4(Alf[1], sa_lo + (uint32_t)((arow + 16) * ROWB + acol));
            int bcol = s * 32 + bcolh;
            #pragma unroll
            for (int np = 0; np < 4; np++) {
                uint32_t Bhf[4], Blf[4];
                uint32_t ba = (uint32_t)((brow + np * 16) * ROWB + bcol);
                ldsm_x4(Bhf, sb_hi + ba);
                ldsm_x4(Blf, sb_lo + ba);
                #pragma unroll
                for (int mt = 0; mt < 2; mt++) {
                    if (HALF) {
                        mma_f16(acc[mt][2 * np],     Ahf[mt], Bhf);
                        mma_f16(acc[mt][2 * np],     Ahf[mt], Blf);
                        mma_f16(acc[mt][2 * np],     Alf[mt], Bhf);
                        mma_f16(acc[mt][2 * np + 1], Ahf[mt], Bhf + 2);
                        mma_f16(acc[mt][2 * np + 1], Ahf[mt], Blf + 2);
                        mma_f16(acc[mt][2 * np + 1], Alf[mt], Bhf + 2);
                    } else {
                        mma_bf16(acc[mt][2 * np],     Ahf[mt], Bhf);
                        mma_bf16(acc[mt][2 * np],     Ahf[mt], Blf);
                        mma_bf16(acc[mt][2 * np],     Alf[mt], Bhf);
                        mma_bf16(acc[mt][2 * np + 1], Ahf[mt], Bhf + 2);
                        mma_bf16(acc[mt][2 * np + 1], Ahf[mt], Blf + 2);
                        mma_bf16(acc[mt][2 * np + 1], Alf[mt], Bhf + 2);
                    }
                }
            }
        }
        __syncthreads();
    }
}

// proj = cb @ w_out^T   (M=8192, N=1024, K=256, bf16 3-pass)
__global__ __launch_bounds__(256, 2)
void k_proj()
{
    extern __shared__ __align__(16) char smem_raw[];
    uint32_t sbase = smem_u32(smem_raw);

    int tid  = threadIdx.x;
    int wid  = tid >> 5;
    int lane = tid & 31;
    int wm   = wid >> 1;
    int wn   = wid & 1;
    int n0   = blockIdx.x * 128;
    int m0   = blockIdx.y * 128;

    float acc[2][8][4];
    #pragma unroll
    for (int mt = 0; mt < 2; mt++)
        #pragma unroll
        for (int nt = 0; nt < 8; nt++)
            #pragma unroll
            for (int j = 0; j < 4; j++) acc[mt][nt][j] = 0.f;

    hmma4_loop<DCB, false>(sbase, m0, n0, tid, g_cb_hi, g_cb_lo, g_wo_hi, g_wo_lo, acc);

    int q  = lane >> 2;
    int qq = lane & 3;
    #pragma unroll
    for (int mt = 0; mt < 2; mt++) {
        int RB = m0 + wm * 32 + mt * 16;
        #pragma unroll
        for (int h = 0; h < 2; h++) {
            int row = RB + h * 8 + q;
            float* pw = g_proj + (size_t)row * DIN + n0;
            #pragma unroll
            for (int nt = 0; nt < 8; nt++) {
                int c0 = wn * 64 + nt * 8 + qq * 2;
                *(float2*)(pw + c0) = make_float2(acc[mt][nt][h * 2 + 0],
                                                  acc[mt][nt][h * 2 + 1]);
            }
        }
    }
}

// z_e = w_in @ z + in_b  (M=256 ch, N=1024 tok/batch, K=1024, fp16 3-pass)
__global__ __launch_bounds__(256, 2)
void k_zein(const float* __restrict__ bias)
{
    extern __shared__ __align__(16) char smem_raw[];
    uint32_t sbase = smem_u32(smem_raw);

    int tid  = threadIdx.x;
    int wid  = tid >> 5;
    int lane = tid & 31;
    int wm   = wid >> 1;
    int wn   = wid & 1;
    int n0   = blockIdx.x * 128;     // token within batch
    int m0   = blockIdx.y * 128;     // channel
    int b    = blockIdx.z;

    const __half* zh = g_z_hi + (size_t)b * TT * DIN;
    const __half* zl = g_z_lo + (size_t)b * TT * DIN;

    float acc[2][8][4];
    #pragma unroll
    for (int mt = 0; mt < 2; mt++)
        #pragma unroll
        for (int nt = 0; nt < 8; nt++)
            #pragma unroll
            for (int j = 0; j < 4; j++) acc[mt][nt][j] = 0.f;

    hmma4_loop<DIN, true>(sbase, m0, n0, tid, g_wi_hi, g_wi_lo, zh, zl, acc);

    int q  = lane >> 2;
    int qq = lane & 3;
    float* C = g_ze + (size_t)b * DCB * TT;
    #pragma unroll
    for (int mt = 0; mt < 2; mt++) {
        int RB = m0 + wm * 32 + mt * 16;
        #pragma unroll
        for (int h = 0; h < 2; h++) {
            int row = RB + h * 8 + q;
            float bb = bias[row];
            float* cw = C + (size_t)row * TT + n0;
            #pragma unroll
            for (int nt = 0; nt < 8; nt++) {
                int c0 = wn * 64 + nt * 8 + qq * 2;
                *(float2*)(cw + c0) = make_float2(acc[mt][nt][h * 2 + 0] + bb,
                                                  acc[mt][nt][h * 2 + 1] + bb);
            }
        }
    }
}

// ---------------- argmin refinement (near-exact fp32) + fused loss ----------
__global__ void k_refine(float* __restrict__ dout, int noff)
{
    int warp = threadIdx.x >> 5;
    int lane = threadIdx.x & 31;
    int n = noff + blockIdx.x * 8 + warp;

    const unsigned long long* tm = g_tilemin + (size_t)n * 128;
    unsigned long long best = tm[lane];
    {
        unsigned long long v;
        v = tm[lane + 32]; if (v < best) best = v;
        v = tm[lane + 64]; if (v < best) best = v;
        v = tm[lane + 96]; if (v < best) best = v;
        #pragma unroll
        for (int off = 16; off; off >>= 1) {
            unsigned long long o = __shfl_xor_sync(0xFFFFFFFFu, best, off);
            if (o < best) best = o;
        }
    }
    float dmin = funkey((unsigned)(best >> 32));
    float thresh = dmin + 8e-3f;

    float inv = g_inv[n];
    float rsq = g_rowsq[n];
    float ev[8];
    {
        const __nv_bfloat16* ah = g_a_hi + (size_t)n * DCB + lane * 8;
        const __nv_bfloat16* al = g_a_lo + (size_t)n * DCB + lane * 8;
        #pragma unroll
        for (int j = 0; j < 8; j++)
            ev[j] = __bfloat162float(ah[j]) + __bfloat162float(al[j]);
    }

    const float* distrow = dout + OFF_DIST + (size_t)n * KK;

    float bestd = 3.4e38f;
    int   bestk = KK;
    float bestpart = 0.f;

    for (int ti = 0; ti < 128; ti++) {
        float tmin = funkey((unsigned)(tm[ti] >> 32));
        if (tmin > thresh) continue;
        int k0 = ti * 64;
        float d0 = distrow[k0 + lane];
        float d1 = distrow[k0 + 32 + lane];
        #pragma unroll
        for (int half = 0; half < 2; half++) {
            float dv = (half == 0) ? d0 : d1;
            unsigned mask = __ballot_sync(0xFFFFFFFFu, dv <= thresh);
            while (mask) {
                int j = __ffs(mask) - 1;
                mask &= mask - 1;
                int k = k0 + half * 32 + j;
                const float* cr = g_cbn + (size_t)k * DCB + lane * 8;
                float part = 0.f;
                #pragma unroll
                for (int qv = 0; qv < 8; qv++)
                    part += ev[qv] * cr[qv];
                #pragma unroll
                for (int off = 16; off; off >>= 1)
                    part += __shfl_xor_sync(0xFFFFFFFFu, part, off);
                float de = rsq + g_colsq[k] - 2.f * part;
                if (de < bestd || (de == bestd && k < bestk)) {
                    bestd = de; bestk = k; bestpart = part;
                }
            }
        }
    }

    if (lane == 0) {
        g_idx[n] = bestk;
        dout[OFF_IDX + n] = (float)bestk;
        atomicAdd(&g_counts[bestk], 1);
        float dot_raw = bestpart / (inv * g_cbinv[bestk]);
        g_lossn[n] = g_rowsq_raw[n] + g_cbsq[bestk] - 2.f * dot_raw;
    }
}

// ---------------- z_q_out gather ----------------
__global__ void k_gather(const float* __restrict__ outb, float* __restrict__ dout, int boff)
{
    int t  = blockIdx.x * 256 + threadIdx.x;
    int o4 = blockIdx.y * 4;
    int b  = boff + blockIdx.z;
    int idx = g_idx[b * TT + t];
    float4 v = *(const float4*)(g_proj + (size_t)idx * DIN + o4);
    size_t base = OFF_ZQ + (size_t)b * DIN * TT + (size_t)o4 * TT + t;
    dout[base]          = v.x + outb[o4];
    dout[base + TT]     = v.y + outb[o4 + 1];
    dout[base + 2 * TT] = v.z + outb[o4 + 2];
    dout[base + 3 * TT] = v.w + outb[o4 + 3];
}

// ---------------- scalars: losses, perplexity, active ----------------
__global__ void k_final(const float* __restrict__ cs, float* __restrict__ dout)
{
    int tid = threadIdx.x;
    __shared__ float lsum[256];
    {
        int bb = tid >> 4;
        int sl = tid & 15;
        float s = 0.f;
        #pragma unroll 4
        for (int i = 0; i < 64; i++)
            s += g_lossn[bb * TT + sl + i * 16];
        lsum[tid] = s;
    }
    __syncthreads();
    if (tid < BB) {
        float s = 0.f;
        #pragma unroll
        for (int i = 0; i < 16; i++) s += lsum[tid * 16 + i];
        float mean = s / (float)(DCB * TT);
        dout[OFF_COMMIT + tid] = mean * 0.15f;
        dout[OFF_CBL + tid]    = mean;
    }

    float ent = 0.f;
    int   act = 0;
    for (int k = tid; k < KK; k += 256) {
        float cnt = (float)g_counts[k];
        float p   = cnt / (float)NTOK;
        ent += p * logf(p + 1e-10f);
        float ncs = cs[k] * 0.99f + cnt * 0.01f;
        if (ncs > 2.0f) act++;
    }
    __shared__ float se[256];
    __shared__ int   sa[256];
    se[tid] = ent; sa[tid] = act; __syncthreads();
    #pragma unroll
    for (int off = 128; off; off >>= 1) {
        if (tid < off) { se[tid] += se[tid + off]; sa[tid] += sa[tid + off]; }
        __syncthreads();
    }
    if (tid == 0) {
        dout[OFF_PERP] = expf(-se[0]);
        dout[OFF_ACT]  = (float)sa[0];
    }
}

// ---------------- launch (fork-join + split dist/refine overlap) ------------
extern "C" void kernel_launch(void* const* d_in, const int* in_sizes, int n_in,
                              void* d_out, int out_size)
{
    const float* z     = (const float*)d_in[0];
    const float* in_g  = (const float*)d_in[1];
    const float* in_v  = (const float*)d_in[2];
    const float* in_b  = (const float*)d_in[3];
    const float* out_g = (const float*)d_in[4];
    const float* out_v = (const float*)d_in[5];
    const float* out_b = (const float*)d_in[6];
    const float* cb    = (const float*)d_in[7];
    const float* cs    = (const float*)d_in[8];
    float* dout = (float*)d_out;

    static cudaStream_t s2 = nullptr, s3 = nullptr;
    static cudaEvent_t  evF = nullptr, evJ = nullptr, e1 = nullptr, e3 = nullptr;
    if (!s2) {
        cudaStreamCreateWithFlags(&s2, cudaStreamNonBlocking);
        cudaStreamCreateWithFlags(&s3, cudaStreamNonBlocking);
        cudaEventCreateWithFlags(&evF, cudaEventDisableTiming);
        cudaEventCreateWithFlags(&evJ, cudaEventDisableTiming);
        cudaEventCreateWithFlags(&e1,  cudaEventDisableTiming);
        cudaEventCreateWithFlags(&e3,  cudaEventDisableTiming);
        cudaFuncSetAttribute(k_dist, cudaFuncAttributeMaxDynamicSharedMemorySize, SMEM_DIST);
        cudaFuncSetAttribute(k_proj, cudaFuncAttributeMaxDynamicSharedMemorySize, SMEM_P4);
        cudaFuncSetAttribute(k_zein, cudaFuncAttributeMaxDynamicSharedMemorySize, SMEM_P4);
    }

    // fork: stream2 does codebook/w_out prep + proj GEMM
    cudaEventRecord(evF, 0);
    cudaStreamWaitEvent(s2, evF, 0);
    k_prep_cbwo<<<1024 + KK, 256, 0, s2>>>(out_v, out_g, cb);
    {
        dim3 grid(DIN / 128, KK / 128, 1);
        k_proj<<<grid, 256, SMEM_P4, s2>>>();
    }
    cudaEventRecord(evJ, s2);

    // main chain
    k_prep_win<<<256, 256>>>(in_v, in_g);
    {
        dim3 grid(4, 32, BB);
        k_zsplit<<<grid, 256>>>(z);
    }
    {
        dim3 grid(TT / 128, DCB / 128, BB);
        k_zein<<<grid, 256, SMEM_P4>>>(in_b);
    }
    k_toknorm<<<NTOK / 32, 256>>>();

    // join with prep/proj
    cudaStreamWaitEvent(0, evJ, 0);

    // dist half 1 (tokens 0..8191)
    {
        dim3 grid(KK / 128, 64, 1);
        k_dist<<<grid, 256, SMEM_DIST>>>(dout, 0);
    }
    cudaEventRecord(e1, 0);

    // dist half 2 (tokens 8192..16383) on main, overlapped with refine1/gather1 on s3
    {
        dim3 grid(KK / 128, 64, 1);
        k_dist<<<grid, 256, SMEM_DIST>>>(dout, NTOK / 2);
    }

    cudaStreamWaitEvent(s3, e1, 0);
    k_refine<<<NTOK / 16, 256, 0, s3>>>(dout, 0);
    {
        dim3 grid(4, 256, BB / 2);
        k_gather<<<grid, 256, 0, s3>>>(out_b, dout, 0);
    }
    cudaEventRecord(e3, s3);

    // refine/gather half 2 on main (after dist2)
    k_refine<<<NTOK / 16, 256>>>(dout, NTOK / 2);
    {
        dim3 grid(4, 256, BB / 2);
        k_gather<<<grid, 256>>>(out_b, dout, BB / 2);
    }

    cudaStreamWaitEvent(0, e3, 0);
    k_final<<<1, 256>>>(cs, dout);
}

// round 16
// speedup vs baseline: 1.5800x; 1.5800x over previous
#include <cuda_runtime.h>
#include <cuda_bf16.h>
#include <cuda_fp16.h>
#include <cstdint>
#include <cstddef>

// ---------------- problem constants ----------------
#define BB   16
#define DIN  1024
#define TT   1024
#define KK   8192
#define DCB  256
#define NTOK (BB * TT)          // 16384

// ---------------- output layout (tuple flattened, f32) ----------------
static constexpr size_t OFF_ZQ     = 0;
static constexpr size_t SZ_ZQ      = (size_t)BB * DIN * TT;
static constexpr size_t OFF_IDX    = OFF_ZQ + SZ_ZQ;
static constexpr size_t OFF_COMMIT = OFF_IDX + NTOK;
static constexpr size_t OFF_CBL    = OFF_COMMIT + BB;
static constexpr size_t OFF_DIST   = OFF_CBL + BB;
static constexpr size_t SZ_DIST    = (size_t)NTOK * KK;
static constexpr size_t OFF_PERP   = OFF_DIST + SZ_DIST;
static constexpr size_t OFF_ACT    = OFF_PERP + 1;

// ---------------- scratch (device globals) ----------------
__device__ float g_cbn   [KK * DCB];        // normalized codebook, row-major (refine)
__device__ float g_colsq [KK];              // ||cb_n||^2
__device__ float g_cbsq  [KK];              // ||cb||^2 raw
__device__ float g_cbinv [KK];              // 1/max(||cb||,eps)
__device__ float g_ze    [BB * DCB * TT];
__device__ float g_inv   [NTOK];
__device__ float g_rowsq [NTOK];            // ||enc_n||^2
__device__ float g_rowsq_raw[NTOK];         // ||z_e||^2 raw
__device__ float g_lossn [NTOK];
__device__ int   g_idx   [NTOK];
__device__ int   g_counts[KK];
__device__ float g_proj  [KK * DIN];

// split operands (16B aligned for cp.async)
__device__ __align__(16) __nv_bfloat16 g_a_hi[(size_t)NTOK * DCB];   // enc_n rounded (bf16)
__device__ __align__(16) __nv_bfloat16 g_a_lo[(size_t)NTOK * DCB];   // enc_n residual (refine reconstruct)
__device__ __align__(16) __nv_bfloat16 g_b_hi[(size_t)KK * DCB];     // cb_n rounded (bf16)
__device__ __align__(16) __nv_bfloat16 g_cb_hi[(size_t)KK * DCB];    // raw cb split (bf16)
__device__ __align__(16) __nv_bfloat16 g_cb_lo[(size_t)KK * DCB];
__device__ __align__(16) __nv_bfloat16 g_wo_hi[(size_t)DIN * DCB];   // w_out split (bf16)
__device__ __align__(16) __nv_bfloat16 g_wo_lo[(size_t)DIN * DCB];
// fp16 split operands for z_e GEMM
__device__ __align__(16) __half g_wi_hi[(size_t)DCB * DIN];          // w_in split [c][k]
__device__ __align__(16) __half g_wi_lo[(size_t)DCB * DIN];
__device__ __align__(16) __half g_z_hi[(size_t)NTOK * DIN];          // z transposed [b][t][k]
__device__ __align__(16) __half g_z_lo[(size_t)NTOK * DIN];
// per-(token, 64-code tile) packed min (key<<32 | code), tile = k/64
__device__ unsigned long long g_tilemin[(size_t)NTOK * 128];

// ---------------- helpers ----------------
__device__ __forceinline__ uint32_t smem_u32(const void* p) {
    uint32_t a;
    asm("{ .reg .u64 t; cvta.to.shared.u64 t, %1; cvt.u32.u64 %0, t; }" : "=r"(a) : "l"(p));
    return a;
}
__device__ __forceinline__ void ldsm_x4(uint32_t* r, uint32_t a) {
    asm volatile("ldmatrix.sync.aligned.m8n8.x4.shared.b16 {%0,%1,%2,%3}, [%4];"
        : "=r"(r[0]), "=r"(r[1]), "=r"(r[2]), "=r"(r[3]) : "r"(a));
}
__device__ __forceinline__ void mma_bf16(float* d, const uint32_t* a, const uint32_t* b) {
    asm volatile("mma.sync.aligned.m16n8k16.row.col.f32.bf16.bf16.f32 "
        "{%0,%1,%2,%3}, {%4,%5,%6,%7}, {%8,%9}, {%0,%1,%2,%3};"
        : "+f"(d[0]), "+f"(d[1]), "+f"(d[2]), "+f"(d[3])
        : "r"(a[0]), "r"(a[1]), "r"(a[2]), "r"(a[3]), "r"(b[0]), "r"(b[1]));
}
__device__ __forceinline__ void mma_f16(float* d, const uint32_t* a, const uint32_t* b) {
    asm volatile("mma.sync.aligned.m16n8k16.row.col.f32.f16.f16.f32 "
        "{%0,%1,%2,%3}, {%4,%5,%6,%7}, {%8,%9}, {%0,%1,%2,%3};"
        : "+f"(d[0]), "+f"(d[1]), "+f"(d[2]), "+f"(d[3])
        : "r"(a[0]), "r"(a[1]), "r"(a[2]), "r"(a[3]), "r"(b[0]), "r"(b[1]));
}
#define CP_ASYNC16(dst, src) \
    asm volatile("cp.async.cg.shared.global [%0], [%1], 16;" :: "r"(dst), "l"(src) : "memory")
#define CP_COMMIT() asm volatile("cp.async.commit_group;" ::: "memory")
#define CP_WAIT1()  asm volatile("cp.async.wait_group 1;" ::: "memory")
#define CP_WAIT0()  asm volatile("cp.async.wait_group 0;" ::: "memory")

__device__ __forceinline__ unsigned fkey(float f) {
    unsigned u = __float_as_uint(f);
    return (u & 0x80000000u) ? ~u : (u | 0x80000000u);
}
__device__ __forceinline__ float funkey(unsigned k) {
    unsigned u = (k & 0x80000000u) ? (k ^ 0x80000000u) : ~k;
    return __uint_as_float(u);
}

// ---------------- prep A: w_in weight-norm -> fp16 split, row-major -------
__global__ void k_prep_win(const float* __restrict__ in_v, const float* __restrict__ in_g)
{
    int r   = blockIdx.x;                // 256 blocks
    int tid = threadIdx.x;
    const float* row = in_v + (size_t)r * DIN;
    float v4[4];
    float s = 0.f;
    #pragma unroll
    for (int i = 0; i < 4; i++) { v4[i] = row[tid * 4 + i]; s += v4[i] * v4[i]; }
    __shared__ float sm[256];
    sm[tid] = s; __syncthreads();
    #pragma unroll
    for (int off = 128; off; off >>= 1) {
        if (tid < off) sm[tid] += sm[tid + off];
        __syncthreads();
    }
    float scale = in_g[r] / sqrtf(sm[0]);
    __half2 h2a, h2b, l2a, l2b;
    float w0 = v4[0] * scale, w1 = v4[1] * scale, w2 = v4[2] * scale, w3 = v4[3] * scale;
    h2a = __floats2half2_rn(w0, w1);
    h2b = __floats2half2_rn(w2, w3);
    l2a = __floats2half2_rn(w0 - __half2float(h2a.x), w1 - __half2float(h2a.y));
    l2b = __floats2half2_rn(w2 - __half2float(h2b.x), w3 - __half2float(h2b.y));
    *(uint2*)(g_wi_hi + (size_t)r * DIN + tid * 4) =
        make_uint2(*(uint32_t*)&h2a, *(uint32_t*)&h2b);
    *(uint2*)(g_wi_lo + (size_t)r * DIN + tid * 4) =
        make_uint2(*(uint32_t*)&l2a, *(uint32_t*)&l2b);
}

// ---------------- z transpose + fp16 split:  [b][k][t] -> [b][t][k] -------
__global__ __launch_bounds__(256)
void k_zsplit(const float* __restrict__ z)
{
    __shared__ float tile[256][33];
    int k0 = blockIdx.x * 256;
    int t0 = blockIdx.y * 32;
    int b  = blockIdx.z;
    int tid = threadIdx.x;

    const float* zb = z + (size_t)b * DIN * TT + (size_t)k0 * TT + t0;
    #pragma unroll
    for (int i = 0; i < 32; i++) {
        int idx = tid + i * 256;
        int c = idx >> 5, t = idx & 31;
        tile[c][t] = zb[(size_t)c * TT + t];
    }
    __syncthreads();

    int j    = tid >> 3;               // token 0..31
    int part = tid & 7;                // 32-k slice
    uint32_t hw[16], lw[16];
    #pragma unroll
    for (int i = 0; i < 16; i++) {
        float v0 = tile[part * 32 + 2 * i][j];
        float v1 = tile[part * 32 + 2 * i + 1][j];
        __half2 h2 = __floats2half2_rn(v0, v1);
        __half2 l2 = __floats2half2_rn(v0 - __half2float(h2.x), v1 - __half2float(h2.y));
        hw[i] = *(uint32_t*)&h2;
        lw[i] = *(uint32_t*)&l2;
    }
    size_t base = ((size_t)b * TT + t0 + j) * DIN + k0 + part * 32;
    uint4* zh = (uint4*)(g_z_hi + base);
    uint4* zl = (uint4*)(g_z_lo + base);
    #pragma unroll
    for (int i = 0; i < 4; i++) {
        zh[i] = make_uint4(hw[4*i], hw[4*i+1], hw[4*i+2], hw[4*i+3]);
        zl[i] = make_uint4(lw[4*i], lw[4*i+1], lw[4*i+2], lw[4*i+3]);
    }
}

// ---------------- prep B: w_out + codebook norms & splits (stream 2) --------
__global__ void k_prep_cbwo(const float* __restrict__ out_v, const float* __restrict__ out_g,
                            const float* __restrict__ cb)
{
    int blk = blockIdx.x;
    int tid = threadIdx.x;
    __shared__ float sm[256];

    if (blk < 1024) {                                   // w_out: 1024 rows x 256
        int r = blk;
        const float* row = out_v + (size_t)r * DCB;
        float v = row[tid];
        sm[tid] = v * v; __syncthreads();
        #pragma unroll
        for (int off = 128; off; off >>= 1) {
            if (tid < off) sm[tid] += sm[tid + off];
            __syncthreads();
        }
        float scale = out_g[r] / sqrtf(sm[0]);
        float w = v * scale;
        __nv_bfloat16 hi = __float2bfloat16_rn(w);
        g_wo_hi[(size_t)r * DCB + tid] = hi;
        g_wo_lo[(size_t)r * DCB + tid] = __float2bfloat16_rn(w - __bfloat162float(hi));
    } else {                                            // codebook: 8192 rows x 256
        int r = blk - 1024;
        const float* row = cb + (size_t)r * DCB;
        float v = row[tid];
        sm[tid] = v * v; __syncthreads();
        #pragma unroll
        for (int off = 128; off; off >>= 1) {
            if (tid < off) sm[tid] += sm[tid + off];
            __syncthreads();
        }
        float sumsq = sm[0];
        float inv = 1.f / fmaxf(sqrtf(sumsq), 1e-12f);
        if (tid == 0) {
            g_colsq[r] = sumsq * inv * inv;
            g_cbsq[r]  = sumsq;
            g_cbinv[r] = inv;
            g_counts[r] = 0;
        }
        float vn = v * inv;
        g_cbn[(size_t)r * DCB + tid] = vn;
        g_b_hi[(size_t)r * DCB + tid] = __float2bfloat16_rn(vn);
        __nv_bfloat16 rh = __float2bfloat16_rn(v);
        g_cb_hi[(size_t)r * DCB + tid] = rh;
        g_cb_lo[(size_t)r * DCB + tid] = __float2bfloat16_rn(v - __bfloat162float(rh));
    }
}

// ---------------- per-token norms + bf16 split (coalesced) ----------------
__global__ __launch_bounds__(256)
void k_toknorm()
{
    __shared__ float tile[256][33];
    int blk = blockIdx.x;
    int b   = blk >> 5;
    int t0  = (blk & 31) << 5;
    int tid = threadIdx.x;

    const float* zb = g_ze + (size_t)b * DCB * TT + t0;
    #pragma unroll
    for (int i = 0; i < 32; i++) {
        int idx = tid + i * 256;
        int c = idx >> 5, t = idx & 31;
        tile[c][t] = zb[(size_t)c * TT + t];
    }
    __syncthreads();

    int j    = tid >> 3;
    int part = tid & 7;
    float s = 0.f;
    #pragma unroll
    for (int i = 0; i < 32; i++) {
        float v = tile[part * 32 + i][j];
        s += v * v;
    }
    s += __shfl_xor_sync(0xFFFFFFFFu, s, 4);
    s += __shfl_xor_sync(0xFFFFFFFFu, s, 2);
    s += __shfl_xor_sync(0xFFFFFFFFu, s, 1);
    float inv = 1.f / fmaxf(sqrtf(s), 1e-12f);

    int n = b * TT + t0 + j;
    if (part == 0) {
        g_inv[n] = inv;
        g_rowsq[n] = s * inv * inv;
        g_rowsq_raw[n] = s;
    }

    uint32_t hw[16], lw[16];
    #pragma unroll
    for (int i = 0; i < 16; i++) {
        float v0 = tile[part * 32 + 2 * i][j] * inv;
        float v1 = tile[part * 32 + 2 * i + 1][j] * inv;
        __nv_bfloat162 h2 = __floats2bfloat162_rn(v0, v1);
        float l0 = v0 - __bfloat162float(h2.x);
        float l1 = v1 - __bfloat162float(h2.y);
        __nv_bfloat162 l2 = __floats2bfloat162_rn(l0, l1);
        hw[i] = *(uint32_t*)&h2;
        lw[i] = *(uint32_t*)&l2;
    }
    uint4* ah = (uint4*)(g_a_hi + (size_t)n * DCB + part * 32);
    uint4* al = (uint4*)(g_a_lo + (size_t)n * DCB + part * 32);
    #pragma unroll
    for (int i = 0; i < 4; i++) {
        ah[i] = make_uint4(hw[4*i], hw[4*i+1], hw[4*i+2], hw[4*i+3]);
        al[i] = make_uint4(lw[4*i], lw[4*i+1], lw[4*i+2], lw[4*i+3]);
    }
}

// ---------------- HMMA GEMM tiles ----------------
static constexpr int ROWB      = 80;
static constexpr int MAT_BYTES = 128 * ROWB;          // 10240
static constexpr int STAGE2    = 2 * MAT_BYTES;       // dist: Ahi, Bhi (single pass)
static constexpr int STAGE4    = 4 * MAT_BYTES;       // 3-pass: Ahi, Alo, Bhi, Blo
static constexpr int COLSQ_OFF = 3 * STAGE2;          // 61440
static constexpr int SMEM_DIST = COLSQ_OFF + 128 * 4; // 61952
static constexpr int SMEM_P4   = 2 * STAGE4;          // 81920

// dist loader: 2 matrices (Ahi, Bhi), K stride 256
__device__ __forceinline__ void load_chunk2(uint32_t sbase, int stage, int kc,
                                            int m0, int n0, int tid)
{
    uint32_t st = sbase + stage * STAGE2;
    #pragma unroll
    for (int i = 0; i < 4; i++) {
        int lin = tid + i * 256;            // 0..1023
        int mat = lin >> 9;                 // 0..1
        int r   = (lin >> 2) & 127;
        int c   = lin & 3;
        uint32_t dst = st + mat * MAT_BYTES + (uint32_t)(r * ROWB + c * 16);
        size_t off = ((size_t)((mat == 0 ? m0 : n0) + r) * DCB + kc * 32) * 2 + c * 16;
        const char* src = (mat == 0) ? ((const char*)g_a_hi + off)
                                     : ((const char*)g_b_hi + off);
        CP_ASYNC16(dst, src);
    }
    CP_COMMIT();
}

__global__ __launch_bounds__(256, 2)
void k_dist(float* __restrict__ dout)
{
    extern __shared__ __align__(16) char smem_raw[];
    uint32_t sbase = smem_u32(smem_raw);
    float* colsq_s = (float*)(smem_raw + COLSQ_OFF);

    int tid  = threadIdx.x;
    int wid  = tid >> 5;
    int lane = tid & 31;
    int wm   = wid >> 1;
    int wn   = wid & 1;
    int n0   = blockIdx.x * 128;
    int m0   = blockIdx.y * 128;

    if (tid < 128) colsq_s[tid] = g_colsq[n0 + tid];

    float acc[2][8][4];
    #pragma unroll
    for (int mt = 0; mt < 2; mt++)
        #pragma unroll
        for (int nt = 0; nt < 8; nt++)
            #pragma unroll
            for (int j = 0; j < 4; j++) acc[mt][nt][j] = 0.f;

    load_chunk2(sbase, 0, 0, m0, n0, tid);
    load_chunk2(sbase, 1, 1, m0, n0, tid);

    int arow  = wm * 32 + (lane & 15);
    int acolh = (lane >> 4) * 16;
    int brow  = wn * 64 + ((lane >> 4) << 3) + (lane & 7);
    int bcolh = ((lane >> 3) & 1) * 16;

    int stage = 0;
    for (int kc = 0; kc < 8; kc++) {
        if (kc < 7) { CP_WAIT1(); } else { CP_WAIT0(); }
        __syncthreads();
        if (kc + 2 < 8) {
            int nstage = stage + 2; if (nstage >= 3) nstage -= 3;
            load_chunk2(sbase, nstage, kc + 2, m0, n0, tid);
        }

        uint32_t sa_hi = sbase + stage * STAGE2;
        uint32_t sb_hi = sa_hi + MAT_BYTES;

        #pragma unroll
        for (int s = 0; s < 2; s++) {
            int acol = s * 32 + acolh;
            uint32_t Ahf[2][4];
            ldsm_x4(Ahf[0], sa_hi + (uint32_t)(arow * ROWB + acol));
            ldsm_x4(Ahf[1], sa_hi + (uint32_t)((arow + 16) * ROWB + acol));
            int bcol = s * 32 + bcolh;
            #pragma unroll
            for (int np = 0; np < 4; np++) {
                uint32_t Bhf[4];
                uint32_t ba = (uint32_t)((brow + np * 16) * ROWB + bcol);
                ldsm_x4(Bhf, sb_hi + ba);
                #pragma unroll
                for (int mt = 0; mt < 2; mt++) {
                    mma_bf16(acc[mt][2 * np],     Ahf[mt], Bhf);
                    mma_bf16(acc[mt][2 * np + 1], Ahf[mt], Bhf + 2);
                }
            }
        }
        stage = (stage + 1 == 3) ? 0 : stage + 1;
    }

    int q  = lane >> 2;
    int qq = lane & 3;
    int tileg = blockIdx.x * 2 + wn;
    #pragma unroll
    for (int mt = 0; mt < 2; mt++) {
        int RB = m0 + wm * 32 + mt * 16;
        #pragma unroll
        for (int h = 0; h < 2; h++) {
            int row = RB + h * 8 + q;
            float rsq = g_rowsq[row];
            float* dw = dout + OFF_DIST + (size_t)row * KK + n0;
            unsigned bkey = 0xFFFFFFFFu, bcode = 0;
            #pragma unroll
            for (int nt = 0; nt < 8; nt++) {
                int c0 = wn * 64 + nt * 8 + qq * 2;
                float d0 = rsq + colsq_s[c0]     - 2.f * acc[mt][nt][h * 2 + 0];
                float d1 = rsq + colsq_s[c0 + 1] - 2.f * acc[mt][nt][h * 2 + 1];
                *(float2*)(dw + c0) = make_float2(d0, d1);
                unsigned k0 = fkey(d0), k1 = fkey(d1);
                if (k0 < bkey) { bkey = k0; bcode = (unsigned)(n0 + c0); }
                if (k1 < bkey) { bkey = k1; bcode = (unsigned)(n0 + c0 + 1); }
            }
            unsigned long long p = ((unsigned long long)bkey << 32) | bcode;
            unsigned long long o;
            o = __shfl_xor_sync(0xFFFFFFFFu, p, 1); if (o < p) p = o;
            o = __shfl_xor_sync(0xFFFFFFFFu, p, 2); if (o < p) p = o;
            if (qq == 0) g_tilemin[(size_t)row * 128 + tileg] = p;
        }
    }
}

// ---------------- generic 4-matrix 3-pass HMMA mainloop ----------------
template<int KDIM>
__device__ __forceinline__ void load_chunk4T(uint32_t sbase, int stage, int kc,
                                             int m0, int n0, int tid,
                                             const void* Ah, const void* Al,
                                             const void* Bh, const void* Bl)
{
    uint32_t st = sbase + stage * STAGE4;
    #pragma unroll
    for (int i = 0; i < 8; i++) {
        int lin = tid + i * 256;
        int mat = lin >> 9;
        int r   = (lin >> 2) & 127;
        int c   = lin & 3;
        uint32_t dst = st + mat * MAT_BYTES + (uint32_t)(r * ROWB + c * 16);
        size_t off = ((size_t)((mat < 2 ? m0 : n0) + r) * KDIM + kc * 32) * 2 + c * 16;
        const char* src;
        if      (mat == 0) src = (const char*)Ah + off;
        else if (mat == 1) src = (const char*)Al + off;
        else if (mat == 2) src = (const char*)Bh + off;
        else               src = (const char*)Bl + off;
        CP_ASYNC16(dst, src);
    }
    CP_COMMIT();
}

template<int KDIM, bool HALF>
__device__ __forceinline__ void hmma4_loop(uint32_t sbase, int m0, int n0, int tid,
                                           const void* Ah, const void* Al,
                                           const void* Bh, const void* Bl,
                                           float acc[2][8][4])
{
    int wid  = tid >> 5;
    int lane = tid & 31;
    int wm   = wid >> 1;
    int wn   = wid & 1;

    load_chunk4T<KDIM>(sbase, 0, 0, m0, n0, tid, Ah, Al, Bh, Bl);

    int arow  = wm * 32 + (lane & 15);
    int acolh = (lane >> 4) * 16;
    int brow  = wn * 64 + ((lane >> 4) << 3) + (lane & 7);
    int bcolh = ((lane >> 3) & 1) * 16;

    constexpr int NCH = KDIM / 32;
    for (int kc = 0; kc < NCH; kc++) {
        int st = kc & 1;
        if (kc < NCH - 1) load_chunk4T<KDIM>(sbase, st ^ 1, kc + 1, m0, n0, tid, Ah, Al, Bh, Bl);
        if (kc < NCH - 1) { CP_WAIT1(); } else { CP_WAIT0(); }
        __syncthreads();

        uint32_t sa_hi = sbase + st * STAGE4;
        uint32_t sa_lo = sa_hi + MAT_BYTES;
        uint32_t sb_hi = sa_hi + 2 * MAT_BYTES;
        uint32_t sb_lo = sa_hi + 3 * MAT_BYTES;

        #pragma unroll
        for (int s = 0; s < 2; s++) {
            int acol = s * 32 + acolh;
            uint32_t Ahf[2][4], Alf[2][4];
            ldsm_x4(Ahf[0], sa_hi + (uint32_t)(arow * ROWB + acol));
            ldsm_x4(Ahf[1], sa_hi + (uint32_t)((arow + 16) * ROWB + acol));
            ldsm_x4(Alf[0], sa_lo + (uint32_t)(arow * ROWB + acol));
            ldsm_x4(Alf[1], sa_lo + (uint32_t)((arow + 16) * ROWB + acol));
            int bcol = s * 32 + bcolh;
            #pragma unroll
            for (int np = 0; np < 4; np++) {
                uint32_t Bhf[4], Blf[4];
                uint32_t ba = (uint32_t)((brow + np * 16) * ROWB + bcol);
                ldsm_x4(Bhf, sb_hi + ba);
                ldsm_x4(Blf, sb_lo + ba);
                #pragma unroll
                for (int mt = 0; mt < 2; mt++) {
                    if (HALF) {
                        mma_f16(acc[mt][2 * np],     Ahf[mt], Bhf);
                        mma_f16(acc[mt][2 * np],     Ahf[mt], Blf);
                        mma_f16(acc[mt][2 * np],     Alf[mt], Bhf);
                        mma_f16(acc[mt][2 * np + 1], Ahf[mt], Bhf + 2);
                        mma_f16(acc[mt][2 * np + 1], Ahf[mt], Blf + 2);
                        mma_f16(acc[mt][2 * np + 1], Alf[mt], Bhf + 2);
                    } else {
                        mma_bf16(acc[mt][2 * np],     Ahf[mt], Bhf);
                        mma_bf16(acc[mt][2 * np],     Ahf[mt], Blf);
                        mma_bf16(acc[mt][2 * np],     Alf[mt], Bhf);
                        mma_bf16(acc[mt][2 * np + 1], Ahf[mt], Bhf + 2);
                        mma_bf16(acc[mt][2 * np + 1], Ahf[mt], Blf + 2);
                        mma_bf16(acc[mt][2 * np + 1], Alf[mt], Bhf + 2);
                    }
                }
            }
        }
        __syncthreads();
    }
}

// proj = cb @ w_out^T   (M=8192, N=1024, K=256, bf16 3-pass)
__global__ __launch_bounds__(256, 2)
void k_proj()
{
    extern __shared__ __align__(16) char smem_raw[];
    uint32_t sbase = smem_u32(smem_raw);

    int tid  = threadIdx.x;
    int wid  = tid >> 5;
    int lane = tid & 31;
    int wm   = wid >> 1;
    int wn   = wid & 1;
    int n0   = blockIdx.x * 128;
    int m0   = blockIdx.y * 128;

    float acc[2][8][4];
    #pragma unroll
    for (int mt = 0; mt < 2; mt++)
        #pragma unroll
        for (int nt = 0; nt < 8; nt++)
            #pragma unroll
            for (int j = 0; j < 4; j++) acc[mt][nt][j] = 0.f;

    hmma4_loop<DCB, false>(sbase, m0, n0, tid, g_cb_hi, g_cb_lo, g_wo_hi, g_wo_lo, acc);

    int q  = lane >> 2;
    int qq = lane & 3;
    #pragma unroll
    for (int mt = 0; mt < 2; mt++) {
        int RB = m0 + wm * 32 + mt * 16;
        #pragma unroll
        for (int h = 0; h < 2; h++) {
            int row = RB + h * 8 + q;
            float* pw = g_proj + (size_t)row * DIN + n0;
            #pragma unroll
            for (int nt = 0; nt < 8; nt++) {
                int c0 = wn * 64 + nt * 8 + qq * 2;
                *(float2*)(pw + c0) = make_float2(acc[mt][nt][h * 2 + 0],
                                                  acc[mt][nt][h * 2 + 1]);
            }
        }
    }
}

// z_e = w_in @ z + in_b  (M=256 ch, N=1024 tok/batch, K=1024, fp16 3-pass)
__global__ __launch_bounds__(256, 2)
void k_zein(const float* __restrict__ bias)
{
    extern __shared__ __align__(16) char smem_raw[];
    uint32_t sbase = smem_u32(smem_raw);

    int tid  = threadIdx.x;
    int wid  = tid >> 5;
    int lane = tid & 31;
    int wm   = wid >> 1;
    int wn   = wid & 1;
    int n0   = blockIdx.x * 128;     // token within batch
    int m0   = blockIdx.y * 128;     // channel
    int b    = blockIdx.z;

    const __half* zh = g_z_hi + (size_t)b * TT * DIN;
    const __half* zl = g_z_lo + (size_t)b * TT * DIN;

    float acc[2][8][4];
    #pragma unroll
    for (int mt = 0; mt < 2; mt++)
        #pragma unroll
        for (int nt = 0; nt < 8; nt++)
            #pragma unroll
            for (int j = 0; j < 4; j++) acc[mt][nt][j] = 0.f;

    hmma4_loop<DIN, true>(sbase, m0, n0, tid, g_wi_hi, g_wi_lo, zh, zl, acc);

    int q  = lane >> 2;
    int qq = lane & 3;
    float* C = g_ze + (size_t)b * DCB * TT;
    #pragma unroll
    for (int mt = 0; mt < 2; mt++) {
        int RB = m0 + wm * 32 + mt * 16;
        #pragma unroll
        for (int h = 0; h < 2; h++) {
            int row = RB + h * 8 + q;
            float bb = bias[row];
            float* cw = C + (size_t)row * TT + n0;
            #pragma unroll
            for (int nt = 0; nt < 8; nt++) {
                int c0 = wn * 64 + nt * 8 + qq * 2;
                *(float2*)(cw + c0) = make_float2(acc[mt][nt][h * 2 + 0] + bb,
                                                  acc[mt][nt][h * 2 + 1] + bb);
            }
        }
    }
}

// ---------------- argmin refinement (near-exact fp32) + fused loss ----------
__global__ void k_refine(float* __restrict__ dout)
{
    int warp = threadIdx.x >> 5;
    int lane = threadIdx.x & 31;
    int n = blockIdx.x * 8 + warp;

    const unsigned long long* tm = g_tilemin + (size_t)n * 128;
    unsigned long long best = tm[lane];
    {
        unsigned long long v;
        v = tm[lane + 32]; if (v < best) best = v;
        v = tm[lane + 64]; if (v < best) best = v;
        v = tm[lane + 96]; if (v < best) best = v;
        #pragma unroll
        for (int off = 16; off; off >>= 1) {
            unsigned long long o = __shfl_xor_sync(0xFFFFFFFFu, best, off);
            if (o < best) best = o;
        }
    }
    float dmin = funkey((unsigned)(best >> 32));
    float thresh = dmin + 8e-3f;

    float inv = g_inv[n];
    float rsq = g_rowsq[n];
    float ev[8];
    {
        const __nv_bfloat16* ah = g_a_hi + (size_t)n * DCB + lane * 8;
        const __nv_bfloat16* al = g_a_lo + (size_t)n * DCB + lane * 8;
        #pragma unroll
        for (int j = 0; j < 8; j++)
            ev[j] = __bfloat162float(ah[j]) + __bfloat162float(al[j]);
    }

    const float* distrow = dout + OFF_DIST + (size_t)n * KK;

    float bestd = 3.4e38f;
    int   bestk = KK;
    float bestpart = 0.f;

    for (int ti = 0; ti < 128; ti++) {
        float tmin = funkey((unsigned)(tm[ti] >> 32));
        if (tmin > thresh) continue;
        int k0 = ti * 64;
        float d0 = distrow[k0 + lane];
        float d1 = distrow[k0 + 32 + lane];
        #pragma unroll
        for (int half = 0; half < 2; half++) {
            float dv = (half == 0) ? d0 : d1;
            unsigned mask = __ballot_sync(0xFFFFFFFFu, dv <= thresh);
            while (mask) {
                int j = __ffs(mask) - 1;
                mask &= mask - 1;
                int k = k0 + half * 32 + j;
                const float* cr = g_cbn + (size_t)k * DCB + lane * 8;
                float part = 0.f;
                #pragma unroll
                for (int qv = 0; qv < 8; qv++)
                    part += ev[qv] * cr[qv];
                #pragma unroll
                for (int off = 16; off; off >>= 1)
                    part += __shfl_xor_sync(0xFFFFFFFFu, part, off);
                float de = rsq + g_colsq[k] - 2.f * part;
                if (de < bestd || (de == bestd && k < bestk)) {
                    bestd = de; bestk = k; bestpart = part;
                }
            }
        }
    }

    if (lane == 0) {
        g_idx[n] = bestk;
        dout[OFF_IDX + n] = (float)bestk;
        atomicAdd(&g_counts[bestk], 1);
        float dot_raw = bestpart / (inv * g_cbinv[bestk]);
        g_lossn[n] = g_rowsq_raw[n] + g_cbsq[bestk] - 2.f * dot_raw;
    }
}

// ---------------- z_q_out gather ----------------
__global__ void k_gather(const float* __restrict__ outb, float* __restrict__ dout)
{
    int t  = blockIdx.x * 256 + threadIdx.x;
    int o4 = blockIdx.y * 4;
    int b  = blockIdx.z;
    int idx = g_idx[b * TT + t];
    float4 v = *(const float4*)(g_proj + (size_t)idx * DIN + o4);
    size_t base = OFF_ZQ + (size_t)b * DIN * TT + (size_t)o4 * TT + t;
    dout[base]          = v.x + outb[o4];
    dout[base + TT]     = v.y + outb[o4 + 1];
    dout[base + 2 * TT] = v.z + outb[o4 + 2];
    dout[base + 3 * TT] = v.w + outb[o4 + 3];
}

// ---------------- scalars: losses, perplexity, active ----------------
__global__ void k_final(const float* __restrict__ cs, float* __restrict__ dout)
{
    int tid = threadIdx.x;
    __shared__ float lsum[256];
    {
        int bb = tid >> 4;
        int sl = tid & 15;
        float s = 0.f;
        #pragma unroll 4
        for (int i = 0; i < 64; i++)
            s += g_lossn[bb * TT + sl + i * 16];
        lsum[tid] = s;
    }
    __syncthreads();
    if (tid < BB) {
        float s = 0.f;
        #pragma unroll
        for (int i = 0; i < 16; i++) s += lsum[tid * 16 + i];
        float mean = s / (float)(DCB * TT);
        dout[OFF_COMMIT + tid] = mean * 0.15f;
        dout[OFF_CBL + tid]    = mean;
    }

    float ent = 0.f;
    int   act = 0;
    for (int k = tid; k < KK; k += 256) {
        float cnt = (float)g_counts[k];
        float p   = cnt / (float)NTOK;
        ent += p * logf(p + 1e-10f);
        float ncs = cs[k] * 0.99f + cnt * 0.01f;
        if (ncs > 2.0f) act++;
    }
    __shared__ float se[256];
    __shared__ int   sa[256];
    se[tid] = ent; sa[tid] = act; __syncthreads();
    #pragma unroll
    for (int off = 128; off; off >>= 1) {
        if (tid < off) { se[tid] += se[tid + off]; sa[tid] += sa[tid + off]; }
        __syncthreads();
    }
    if (tid == 0) {
        dout[OFF_PERP] = expf(-se[0]);
        dout[OFF_ACT]  = (float)sa[0];
    }
}

// ---------------- launch (fork-join, fine-grained join events) --------------
extern "C" void kernel_launch(void* const* d_in, const int* in_sizes, int n_in,
                              void* d_out, int out_size)
{
    const float* z     = (const float*)d_in[0];
    const float* in_g  = (const float*)d_in[1];
    const float* in_v  = (const float*)d_in[2];
    const float* in_b  = (const float*)d_in[3];
    const float* out_g = (const float*)d_in[4];
    const float* out_v = (const float*)d_in[5];
    const float* out_b = (const float*)d_in[6];
    const float* cb    = (const float*)d_in[7];
    const float* cs    = (const float*)d_in[8];
    float* dout = (float*)d_out;

    static cudaStream_t s2 = nullptr;
    static cudaEvent_t  evF = nullptr, evW = nullptr, evP = nullptr, evJ = nullptr;
    if (!s2) {
        cudaStreamCreateWithFlags(&s2, cudaStreamNonBlocking);
        cudaEventCreateWithFlags(&evF, cudaEventDisableTiming);
        cudaEventCreateWithFlags(&evW, cudaEventDisableTiming);
        cudaEventCreateWithFlags(&evP, cudaEventDisableTiming);
        cudaEventCreateWithFlags(&evJ, cudaEventDisableTiming);
        cudaFuncSetAttribute(k_dist, cudaFuncAttributeMaxDynamicSharedMemorySize, SMEM_DIST);
        cudaFuncSetAttribute(k_proj, cudaFuncAttributeMaxDynamicSharedMemorySize, SMEM_P4);
        cudaFuncSetAttribute(k_zein, cudaFuncAttributeMaxDynamicSharedMemorySize, SMEM_P4);
    }

    // fork: stream2 does ALL weight prep + proj GEMM
    cudaEventRecord(evF, 0);
    cudaStreamWaitEvent(s2, evF, 0);
    k_prep_win<<<256, 256, 0, s2>>>(in_v, in_g);
    cudaEventRecord(evW, s2);                       // w_in split ready
    k_prep_cbwo<<<1024 + KK, 256, 0, s2>>>(out_v, out_g, cb);
    cudaEventRecord(evP, s2);                       // b_hi/colsq/cbn ready
    {
        dim3 grid(DIN / 128, KK / 128, 1);
        k_proj<<<grid, 256, SMEM_P4, s2>>>();
    }
    cudaEventRecord(evJ, s2);                       // proj ready

    // main chain
    {
        dim3 grid(4, 32, BB);
        k_zsplit<<<grid, 256>>>(z);
    }
    cudaStreamWaitEvent(0, evW, 0);                 // zein needs g_wi_*
    {
        dim3 grid(TT / 128, DCB / 128, BB);
        k_zein<<<grid, 256, SMEM_P4>>>(in_b);
    }
    k_toknorm<<<NTOK / 32, 256>>>();

    cudaStreamWaitEvent(0, evP, 0);                 // dist needs g_b_hi/g_colsq
    {
        dim3 grid(KK / 128, NTOK / 128, 1);
        k_dist<<<grid, 256, SMEM_DIST>>>(dout);
    }
    k_refine<<<NTOK / 8, 256>>>(dout);              // needs g_cbn (covered by evP)

    cudaStreamWaitEvent(0, evJ, 0);                 // gather needs g_proj
    {
        dim3 grid(4, 256, BB);
        k_gather<<<grid, 256>>>(out_b, dout);
    }
    k_final<<<1, 256>>>(cs, dout);
}

// round 17
// speedup vs baseline: 1.6043x; 1.0154x over previous
#include <cuda_runtime.h>
#include <cuda_bf16.h>
#include <cuda_fp16.h>
#include <cstdint>
#include <cstddef>

// ---------------- problem constants ----------------
#define BB   16
#define DIN  1024
#define TT   1024
#define KK   8192
#define DCB  256
#define NTOK (BB * TT)          // 16384

// ---------------- output layout (tuple flattened, f32) ----------------
static constexpr size_t OFF_ZQ     = 0;
static constexpr size_t SZ_ZQ      = (size_t)BB * DIN * TT;
static constexpr size_t OFF_IDX    = OFF_ZQ + SZ_ZQ;
static constexpr size_t OFF_COMMIT = OFF_IDX + NTOK;
static constexpr size_t OFF_CBL    = OFF_COMMIT + BB;
static constexpr size_t OFF_DIST   = OFF_CBL + BB;
static constexpr size_t SZ_DIST    = (size_t)NTOK * KK;
static constexpr size_t OFF_PERP   = OFF_DIST + SZ_DIST;
static constexpr size_t OFF_ACT    = OFF_PERP + 1;

// ---------------- scratch (device globals) ----------------
__device__ float g_cbn   [KK * DCB];        // normalized codebook, row-major (refine)
__device__ float g_colsq [KK];              // ||cb_n||^2
__device__ float g_cbsq  [KK];              // ||cb||^2 raw
__device__ float g_cbinv [KK];              // 1/max(||cb||,eps)
__device__ float g_ze    [BB * DCB * TT];
__device__ float g_inv   [NTOK];
__device__ float g_rowsq [NTOK];            // ||enc_n||^2
__device__ float g_rowsq_raw[NTOK];         // ||z_e||^2 raw
__device__ float g_lossn [NTOK];
__device__ int   g_idx   [NTOK];
__device__ int   g_counts[KK];
__device__ float g_proj  [KK * DIN];

// split operands (16B aligned for cp.async)
__device__ __align__(16) __nv_bfloat16 g_a_hi[(size_t)NTOK * DCB];   // enc_n rounded (bf16)
__device__ __align__(16) __nv_bfloat16 g_a_lo[(size_t)NTOK * DCB];   // enc_n residual (refine reconstruct)
__device__ __align__(16) __nv_bfloat16 g_b_hi[(size_t)KK * DCB];     // cb_n rounded (bf16)
__device__ __align__(16) __nv_bfloat16 g_cb_hi[(size_t)KK * DCB];    // raw cb split (bf16)
__device__ __align__(16) __nv_bfloat16 g_cb_lo[(size_t)KK * DCB];
__device__ __align__(16) __nv_bfloat16 g_wo_hi[(size_t)DIN * DCB];   // w_out split (bf16)
__device__ __align__(16) __nv_bfloat16 g_wo_lo[(size_t)DIN * DCB];
// fp16 split operands for z_e GEMM
__device__ __align__(16) __half g_wi_hi[(size_t)DCB * DIN];          // w_in split [c][k]
__device__ __align__(16) __half g_wi_lo[(size_t)DCB * DIN];
__device__ __align__(16) __half g_z_hi[(size_t)NTOK * DIN];          // z transposed [b][t][k]
__device__ __align__(16) __half g_z_lo[(size_t)NTOK * DIN];
// per-(token, 64-code tile) packed min (key<<32 | code), tile = k/64
__device__ unsigned long long g_tilemin[(size_t)NTOK * 128];

// ---------------- helpers ----------------
__device__ __forceinline__ uint32_t smem_u32(const void* p) {
    uint32_t a;
    asm("{ .reg .u64 t; cvta.to.shared.u64 t, %1; cvt.u32.u64 %0, t; }" : "=r"(a) : "l"(p));
    return a;
}
__device__ __forceinline__ void ldsm_x4(uint32_t* r, uint32_t a) {
    asm volatile("ldmatrix.sync.aligned.m8n8.x4.shared.b16 {%0,%1,%2,%3}, [%4];"
        : "=r"(r[0]), "=r"(r[1]), "=r"(r[2]), "=r"(r[3]) : "r"(a));
}
__device__ __forceinline__ void mma_bf16(float* d, const uint32_t* a, const uint32_t* b) {
    asm volatile("mma.sync.aligned.m16n8k16.row.col.f32.bf16.bf16.f32 "
        "{%0,%1,%2,%3}, {%4,%5,%6,%7}, {%8,%9}, {%0,%1,%2,%3};"
        : "+f"(d[0]), "+f"(d[1]), "+f"(d[2]), "+f"(d[3])
        : "r"(a[0]), "r"(a[1]), "r"(a[2]), "r"(a[3]), "r"(b[0]), "r"(b[1]));
}
__device__ __forceinline__ void mma_f16(float* d, const uint32_t* a, const uint32_t* b) {
    asm volatile("mma.sync.aligned.m16n8k16.row.col.f32.f16.f16.f32 "
        "{%0,%1,%2,%3}, {%4,%5,%6,%7}, {%8,%9}, {%0,%1,%2,%3};"
        : "+f"(d[0]), "+f"(d[1]), "+f"(d[2]), "+f"(d[3])
        : "r"(a[0]), "r"(a[1]), "r"(a[2]), "r"(a[3]), "r"(b[0]), "r"(b[1]));
}
#define CP_ASYNC16(dst, src) \
    asm volatile("cp.async.cg.shared.global [%0], [%1], 16;" :: "r"(dst), "l"(src) : "memory")
#define CP_COMMIT() asm volatile("cp.async.commit_group;" ::: "memory")
#define CP_WAIT1()  asm volatile("cp.async.wait_group 1;" ::: "memory")
#define CP_WAIT0()  asm volatile("cp.async.wait_group 0;" ::: "memory")

__device__ __forceinline__ void stg_cs_f2(float* p, float a, float b) {
    asm volatile("st.global.cs.v2.f32 [%0], {%1, %2};" :: "l"(p), "f"(a), "f"(b) : "memory");
}

__device__ __forceinline__ unsigned fkey(float f) {
    unsigned u = __float_as_uint(f);
    return (u & 0x80000000u) ? ~u : (u | 0x80000000u);
}
__device__ __forceinline__ float funkey(unsigned k) {
    unsigned u = (k & 0x80000000u) ? (k ^ 0x80000000u) : ~k;
    return __uint_as_float(u);
}

// ---------------- prep A: w_in weight-norm -> fp16 split, row-major -------
__global__ void k_prep_win(const float* __restrict__ in_v, const float* __restrict__ in_g)
{
    int r   = blockIdx.x;                // 256 blocks
    int tid = threadIdx.x;
    const float* row = in_v + (size_t)r * DIN;
    float v4[4];
    float s = 0.f;
    #pragma unroll
    for (int i = 0; i < 4; i++) { v4[i] = row[tid * 4 + i]; s += v4[i] * v4[i]; }
    __shared__ float sm[256];
    sm[tid] = s; __syncthreads();
    #pragma unroll
    for (int off = 128; off; off >>= 1) {
        if (tid < off) sm[tid] += sm[tid + off];
        __syncthreads();
    }
    float scale = in_g[r] / sqrtf(sm[0]);
    __half2 h2a, h2b, l2a, l2b;
    float w0 = v4[0] * scale, w1 = v4[1] * scale, w2 = v4[2] * scale, w3 = v4[3] * scale;
    h2a = __floats2half2_rn(w0, w1);
    h2b = __floats2half2_rn(w2, w3);
    l2a = __floats2half2_rn(w0 - __half2float(h2a.x), w1 - __half2float(h2a.y));
    l2b = __floats2half2_rn(w2 - __half2float(h2b.x), w3 - __half2float(h2b.y));
    *(uint2*)(g_wi_hi + (size_t)r * DIN + tid * 4) =
        make_uint2(*(uint32_t*)&h2a, *(uint32_t*)&h2b);
    *(uint2*)(g_wi_lo + (size_t)r * DIN + tid * 4) =
        make_uint2(*(uint32_t*)&l2a, *(uint32_t*)&l2b);
}

// ---------------- z transpose + fp16 split:  [b][k][t] -> [b][t][k] -------
__global__ __launch_bounds__(256)
void k_zsplit(const float* __restrict__ z)
{
    __shared__ float tile[256][33];
    int k0 = blockIdx.x * 256;
    int t0 = blockIdx.y * 32;
    int b  = blockIdx.z;
    int tid = threadIdx.x;

    const float* zb = z + (size_t)b * DIN * TT + (size_t)k0 * TT + t0;
    #pragma unroll
    for (int i = 0; i < 32; i++) {
        int idx = tid + i * 256;
        int c = idx >> 5, t = idx & 31;
        tile[c][t] = zb[(size_t)c * TT + t];
    }
    __syncthreads();

    int j    = tid >> 3;               // token 0..31
    int part = tid & 7;                // 32-k slice
    uint32_t hw[16], lw[16];
    #pragma unroll
    for (int i = 0; i < 16; i++) {
        float v0 = tile[part * 32 + 2 * i][j];
        float v1 = tile[part * 32 + 2 * i + 1][j];
        __half2 h2 = __floats2half2_rn(v0, v1);
        __half2 l2 = __floats2half2_rn(v0 - __half2float(h2.x), v1 - __half2float(h2.y));
        hw[i] = *(uint32_t*)&h2;
        lw[i] = *(uint32_t*)&l2;
    }
    size_t base = ((size_t)b * TT + t0 + j) * DIN + k0 + part * 32;
    uint4* zh = (uint4*)(g_z_hi + base);
    uint4* zl = (uint4*)(g_z_lo + base);
    #pragma unroll
    for (int i = 0; i < 4; i++) {
        zh[i] = make_uint4(hw[4*i], hw[4*i+1], hw[4*i+2], hw[4*i+3]);
        zl[i] = make_uint4(lw[4*i], lw[4*i+1], lw[4*i+2], lw[4*i+3]);
    }
}

// ---------------- prep B: w_out + codebook norms & splits (stream 2) --------
__global__ void k_prep_cbwo(const float* __restrict__ out_v, const float* __restrict__ out_g,
                            const float* __restrict__ cb)
{
    int blk = blockIdx.x;
    int tid = threadIdx.x;
    __shared__ float sm[256];

    if (blk < 1024) {                                   // w_out: 1024 rows x 256
        int r = blk;
        const float* row = out_v + (size_t)r * DCB;
        float v = row[tid];
        sm[tid] = v * v; __syncthreads();
        #pragma unroll
        for (int off = 128; off; off >>= 1) {
            if (tid < off) sm[tid] += sm[tid + off];
            __syncthreads();
        }
        float scale = out_g[r] / sqrtf(sm[0]);
        float w = v * scale;
        __nv_bfloat16 hi = __float2bfloat16_rn(w);
        g_wo_hi[(size_t)r * DCB + tid] = hi;
        g_wo_lo[(size_t)r * DCB + tid] = __float2bfloat16_rn(w - __bfloat162float(hi));
    } else {                                            // codebook: 8192 rows x 256
        int r = blk - 1024;
        const float* row = cb + (size_t)r * DCB;
        float v = row[tid];
        sm[tid] = v * v; __syncthreads();
        #pragma unroll
        for (int off = 128; off; off >>= 1) {
            if (tid < off) sm[tid] += sm[tid + off];
            __syncthreads();
        }
        float sumsq = sm[0];
        float inv = 1.f / fmaxf(sqrtf(sumsq), 1e-12f);
        if (tid == 0) {
            g_colsq[r] = sumsq * inv * inv;
            g_cbsq[r]  = sumsq;
            g_cbinv[r] = inv;
            g_counts[r] = 0;
        }
        float vn = v * inv;
        g_cbn[(size_t)r * DCB + tid] = vn;
        g_b_hi[(size_t)r * DCB + tid] = __float2bfloat16_rn(vn);
        __nv_bfloat16 rh = __float2bfloat16_rn(v);
        g_cb_hi[(size_t)r * DCB + tid] = rh;
        g_cb_lo[(size_t)r * DCB + tid] = __float2bfloat16_rn(v - __bfloat162float(rh));
    }
}

// ---------------- per-token norms + bf16 split (coalesced) ----------------
__global__ __launch_bounds__(256)
void k_toknorm()
{
    __shared__ float tile[256][33];
    int blk = blockIdx.x;
    int b   = blk >> 5;
    int t0  = (blk & 31) << 5;
    int tid = threadIdx.x;

    const float* zb = g_ze + (size_t)b * DCB * TT + t0;
    #pragma unroll
    for (int i = 0; i < 32; i++) {
        int idx = tid + i * 256;
        int c = idx >> 5, t = idx & 31;
        tile[c][t] = zb[(size_t)c * TT + t];
    }
    __syncthreads();

    int j    = tid >> 3;
    int part = tid & 7;
    float s = 0.f;
    #pragma unroll
    for (int i = 0; i < 32; i++) {
        float v = tile[part * 32 + i][j];
        s += v * v;
    }
    s += __shfl_xor_sync(0xFFFFFFFFu, s, 4);
    s += __shfl_xor_sync(0xFFFFFFFFu, s, 2);
    s += __shfl_xor_sync(0xFFFFFFFFu, s, 1);
    float inv = 1.f / fmaxf(sqrtf(s), 1e-12f);

    int n = b * TT + t0 + j;
    if (part == 0) {
        g_inv[n] = inv;
        g_rowsq[n] = s * inv * inv;
        g_rowsq_raw[n] = s;
    }

    uint32_t hw[16], lw[16];
    #pragma unroll
    for (int i = 0; i < 16; i++) {
        float v0 = tile[part * 32 + 2 * i][j] * inv;
        float v1 = tile[part * 32 + 2 * i + 1][j] * inv;
        __nv_bfloat162 h2 = __floats2bfloat162_rn(v0, v1);
        float l0 = v0 - __bfloat162float(h2.x);
        float l1 = v1 - __bfloat162float(h2.y);
        __nv_bfloat162 l2 = __floats2bfloat162_rn(l0, l1);
        hw[i] = *(uint32_t*)&h2;
        lw[i] = *(uint32_t*)&l2;
    }
    uint4* ah = (uint4*)(g_a_hi + (size_t)n * DCB + part * 32);
    uint4* al = (uint4*)(g_a_lo + (size_t)n * DCB + part * 32);
    #pragma unroll
    for (int i = 0; i < 4; i++) {
        ah[i] = make_uint4(hw[4*i], hw[4*i+1], hw[4*i+2], hw[4*i+3]);
        al[i] = make_uint4(lw[4*i], lw[4*i+1], lw[4*i+2], lw[4*i+3]);
    }
}

// ---------------- HMMA GEMM tiles ----------------
// dist uses 64-ch K-chunks (ROWB_D = 144); proj/zein keep 32-ch (ROWB = 80)
static constexpr int ROWB      = 80;
static constexpr int MAT_BYTES = 128 * ROWB;          // 10240
static constexpr int ROWB_D    = 144;                 // 128B data + 16B pad
static constexpr int MAT_D     = 128 * ROWB_D;        // 18432
static constexpr int STAGE2    = 2 * MAT_D;           // dist: Ahi, Bhi (64-ch chunk)
static constexpr int STAGE4    = 4 * MAT_BYTES;       // 3-pass: Ahi, Alo, Bhi, Blo
static constexpr int COLSQ_OFF = 3 * STAGE2;          // 110592
static constexpr int SMEM_DIST = COLSQ_OFF + 128 * 4; // 111104
static constexpr int SMEM_P4   = 2 * STAGE4;          // 81920

// dist loader: 2 matrices (Ahi, Bhi), 64-channel chunk (128B/row)
__device__ __forceinline__ void load_chunk2(uint32_t sbase, int stage, int kc,
                                            int m0, int n0, int tid)
{
    uint32_t st = sbase + stage * STAGE2;
    #pragma unroll
    for (int i = 0; i < 8; i++) {
        int lin = tid + i * 256;            // 0..2047
        int mat = lin >> 10;                // 0..1
        int r   = (lin >> 3) & 127;
        int c   = lin & 7;
        uint32_t dst = st + mat * MAT_D + (uint32_t)(r * ROWB_D + c * 16);
        size_t off = ((size_t)((mat == 0 ? m0 : n0) + r) * DCB + kc * 64) * 2 + c * 16;
        const char* src = (mat == 0) ? ((const char*)g_a_hi + off)
                                     : ((const char*)g_b_hi + off);
        CP_ASYNC16(dst, src);
    }
    CP_COMMIT();
}

__global__ __launch_bounds__(256, 2)
void k_dist(float* __restrict__ dout)
{
    extern __shared__ __align__(16) char smem_raw[];
    uint32_t sbase = smem_u32(smem_raw);
    float* colsq_s = (float*)(smem_raw + COLSQ_OFF);

    int tid  = threadIdx.x;
    int wid  = tid >> 5;
    int lane = tid & 31;
    int wm   = wid >> 1;
    int wn   = wid & 1;
    int n0   = blockIdx.x * 128;
    int m0   = blockIdx.y * 128;

    if (tid < 128) colsq_s[tid] = g_colsq[n0 + tid];

    float acc[2][8][4];
    #pragma unroll
    for (int mt = 0; mt < 2; mt++)
        #pragma unroll
        for (int nt = 0; nt < 8; nt++)
            #pragma unroll
            for (int j = 0; j < 4; j++) acc[mt][nt][j] = 0.f;

    load_chunk2(sbase, 0, 0, m0, n0, tid);
    load_chunk2(sbase, 1, 1, m0, n0, tid);

    int arow  = wm * 32 + (lane & 15);
    int acolh = (lane >> 4) * 16;
    int brow  = wn * 64 + ((lane >> 4) << 3) + (lane & 7);
    int bcolh = ((lane >> 3) & 1) * 16;

    int stage = 0;
    for (int kc = 0; kc < 4; kc++) {
        if (kc < 3) { CP_WAIT1(); } else { CP_WAIT0(); }
        __syncthreads();
        if (kc + 2 < 4) {
            int nstage = stage + 2; if (nstage >= 3) nstage -= 3;
            load_chunk2(sbase, nstage, kc + 2, m0, n0, tid);
        }

        uint32_t sa_hi = sbase + stage * STAGE2;
        uint32_t sb_hi = sa_hi + MAT_D;

        #pragma unroll
        for (int s = 0; s < 4; s++) {
            int acol = s * 32 + acolh;
            uint32_t Ahf[2][4];
            ldsm_x4(Ahf[0], sa_hi + (uint32_t)(arow * ROWB_D + acol));
            ldsm_x4(Ahf[1], sa_hi + (uint32_t)((arow + 16) * ROWB_D + acol));
            int bcol = s * 32 + bcolh;
            #pragma unroll
            for (int np = 0; np < 4; np++) {
                uint32_t Bhf[4];
                uint32_t ba = (uint32_t)((brow + np * 16) * ROWB_D + bcol);
                ldsm_x4(Bhf, sb_hi + ba);
                #pragma unroll
                for (int mt = 0; mt < 2; mt++) {
                    mma_bf16(acc[mt][2 * np],     Ahf[mt], Bhf);
                    mma_bf16(acc[mt][2 * np + 1], Ahf[mt], Bhf + 2);
                }
            }
        }
        stage = (stage + 1 == 3) ? 0 : stage + 1;
    }

    int q  = lane >> 2;
    int qq = lane & 3;
    int tileg = blockIdx.x * 2 + wn;
    #pragma unroll
    for (int mt = 0; mt < 2; mt++) {
        int RB = m0 + wm * 32 + mt * 16;
        #pragma unroll
        for (int h = 0; h < 2; h++) {
            int row = RB + h * 8 + q;
            float rsq = g_rowsq[row];
            float* dw = dout + OFF_DIST + (size_t)row * KK + n0;
            unsigned bkey = 0xFFFFFFFFu, bcode = 0;
            #pragma unroll
            for (int nt = 0; nt < 8; nt++) {
                int c0 = wn * 64 + nt * 8 + qq * 2;
                float d0 = rsq + colsq_s[c0]     - 2.f * acc[mt][nt][h * 2 + 0];
                float d1 = rsq + colsq_s[c0 + 1] - 2.f * acc[mt][nt][h * 2 + 1];
                stg_cs_f2(dw + c0, d0, d1);
                unsigned k0 = fkey(d0), k1 = fkey(d1);
                if (k0 < bkey) { bkey = k0; bcode = (unsigned)(n0 + c0); }
                if (k1 < bkey) { bkey = k1; bcode = (unsigned)(n0 + c0 + 1); }
            }
            unsigned long long p = ((unsigned long long)bkey << 32) | bcode;
            unsigned long long o;
            o = __shfl_xor_sync(0xFFFFFFFFu, p, 1); if (o < p) p = o;
            o = __shfl_xor_sync(0xFFFFFFFFu, p, 2); if (o < p) p = o;
            if (qq == 0) g_tilemin[(size_t)row * 128 + tileg] = p;
        }
    }
}

// ---------------- generic 4-matrix 3-pass HMMA mainloop ----------------
template<int KDIM>
__device__ __forceinline__ void load_chunk4T(uint32_t sbase, int stage, int kc,
                                             int m0, int n0, int tid,
                                             const void* Ah, const void* Al,
                                             const void* Bh, const void* Bl)
{
    uint32_t st = sbase + stage * STAGE4;
    #pragma unroll
    for (int i = 0; i < 8; i++) {
        int lin = tid + i * 256;
        int mat = lin >> 9;
        int r   = (lin >> 2) & 127;
        int c   = lin & 3;
        uint32_t dst = st + mat * MAT_BYTES + (uint32_t)(r * ROWB + c * 16);
        size_t off = ((size_t)((mat < 2 ? m0 : n0) + r) * KDIM + kc * 32) * 2 + c * 16;
        const char* src;
        if      (mat == 0) src = (const char*)Ah + off;
        else if (mat == 1) src = (const char*)Al + off;
        else if (mat == 2) src = (const char*)Bh + off;
        else               src = (const char*)Bl + off;
        CP_ASYNC16(dst, src);
    }
    CP_COMMIT();
}

template<int KDIM, bool HALF>
__device__ __forceinline__ void hmma4_loop(uint32_t sbase, int m0, int n0, int tid,
                                           const void* Ah, const void* Al,
                                           const void* Bh, const void* Bl,
                                           float acc[2][8][4])
{
    int wid  = tid >> 5;
    int lane = tid & 31;
    int wm   = wid >> 1;
    int wn   = wid & 1;

    load_chunk4T<KDIM>(sbase, 0, 0, m0, n0, tid, Ah, Al, Bh, Bl);

    int arow  = wm * 32 + (lane & 15);
    int acolh = (lane >> 4) * 16;
    int brow  = wn * 64 + ((lane >> 4) << 3) + (lane & 7);
    int bcolh = ((lane >> 3) & 1) * 16;

    constexpr int NCH = KDIM / 32;
    for (int kc = 0; kc < NCH; kc++) {
        int st = kc & 1;
        if (kc < NCH - 1) load_chunk4T<KDIM>(sbase, st ^ 1, kc + 1, m0, n0, tid, Ah, Al, Bh, Bl);
        if (kc < NCH - 1) { CP_WAIT1(); } else { CP_WAIT0(); }
        __syncthreads();

        uint32_t sa_hi = sbase + st * STAGE4;
        uint32_t sa_lo = sa_hi + MAT_BYTES;
        uint32_t sb_hi = sa_hi + 2 * MAT_BYTES;
        uint32_t sb_lo = sa_hi + 3 * MAT_BYTES;

        #pragma unroll
        for (int s = 0; s < 2; s++) {
            int acol = s * 32 + acolh;
            uint32_t Ahf[2][4], Alf[2][4];
            ldsm_x4(Ahf[0], sa_hi + (uint32_t)(arow * ROWB + acol));
            ldsm_x4(Ahf[1], sa_hi + (uint32_t)((arow + 16) * ROWB + acol));
            ldsm_x4(Alf[0], sa_lo + (uint32_t)(arow * ROWB + acol));
            ldsm_x4(Alf[1], sa_lo + (uint32_t)((arow + 16) * ROWB + acol));
            int bcol = s * 32 + bcolh;
            #pragma unroll
            for (int np = 0; np < 4; np++) {
                uint32_t Bhf[4], Blf[4];
                uint32_t ba = (uint32_t)((brow + np * 16) * ROWB + bcol);
                ldsm_x4(Bhf, sb_hi + ba);
                ldsm_x4(Blf, sb_lo + ba);
                #pragma unroll
                for (int mt = 0; mt < 2; mt++) {
                    if (HALF) {
                        mma_f16(acc[mt][2 * np],     Ahf[mt], Bhf);
                        mma_f16(acc[mt][2 * np],     Ahf[mt], Blf);
                        mma_f16(acc[mt][2 * np],     Alf[mt], Bhf);
                        mma_f16(acc[mt][2 * np + 1], Ahf[mt], Bhf + 2);
                        mma_f16(acc[mt][2 * np + 1], Ahf[mt], Blf + 2);
                        mma_f16(acc[mt][2 * np + 1], Alf[mt], Bhf + 2);
                    } else {
                        mma_bf16(acc[mt][2 * np],     Ahf[mt], Bhf);
                        mma_bf16(acc[mt][2 * np],     Ahf[mt], Blf);
                        mma_bf16(acc[mt][2 * np],     Alf[mt], Bhf);
                        mma_bf16(acc[mt][2 * np + 1], Ahf[mt], Bhf + 2);
                        mma_bf16(acc[mt][2 * np + 1], Ahf[mt], Blf + 2);
                        mma_bf16(acc[mt][2 * np + 1], Alf[mt], Bhf + 2);
                    }
                }
            }
        }
        __syncthreads();
    }
}

// proj = cb @ w_out^T   (M=8192, N=1024, K=256, bf16 3-pass)
__global__ __launch_bounds__(256, 2)
void k_proj()
{
    extern __shared__ __align__(16) char smem_raw[];
    uint32_t sbase = smem_u32(smem_raw);

    int tid  = threadIdx.x;
    int wid  = tid >> 5;
    int lane = tid & 31;
    int wm   = wid >> 1;
    int wn   = wid & 1;
    int n0   = blockIdx.x * 128;
    int m0   = blockIdx.y * 128;

    float acc[2][8][4];
    #pragma unroll
    for (int mt = 0; mt < 2; mt++)
        #pragma unroll
        for (int nt = 0; nt < 8; nt++)
            #pragma unroll
            for (int j = 0; j < 4; j++) acc[mt][nt][j] = 0.f;

    hmma4_loop<DCB, false>(sbase, m0, n0, tid, g_cb_hi, g_cb_lo, g_wo_hi, g_wo_lo, acc);

    int q  = lane >> 2;
    int qq = lane & 3;
    #pragma unroll
    for (int mt = 0; mt < 2; mt++) {
        int RB = m0 + wm * 32 + mt * 16;
        #pragma unroll
        for (int h = 0; h < 2; h++) {
            int row = RB + h * 8 + q;
            float* pw = g_proj + (size_t)row * DIN + n0;
            #pragma unroll
            for (int nt = 0; nt < 8; nt++) {
                int c0 = wn * 64 + nt * 8 + qq * 2;
                *(float2*)(pw + c0) = make_float2(acc[mt][nt][h * 2 + 0],
                                                  acc[mt][nt][h * 2 + 1]);
            }
        }
    }
}

// z_e = w_in @ z + in_b  (M=256 ch, N=1024 tok/batch, K=1024, fp16 3-pass)
__global__ __launch_bounds__(256, 2)
void k_zein(const float* __restrict__ bias)
{
    extern __shared__ __align__(16) char smem_raw[];
    uint32_t sbase = smem_u32(smem_raw);

    int tid  = threadIdx.x;
    int wid  = tid >> 5;
    int lane = tid & 31;
    int wm   = wid >> 1;
    int wn   = wid & 1;
    int n0   = blockIdx.x * 128;     // token within batch
    int m0   = blockIdx.y * 128;     // channel
    int b    = blockIdx.z;

    const __half* zh = g_z_hi + (size_t)b * TT * DIN;
    const __half* zl = g_z_lo + (size_t)b * TT * DIN;

    float acc[2][8][4];
    #pragma unroll
    for (int mt = 0; mt < 2; mt++)
        #pragma unroll
        for (int nt = 0; nt < 8; nt++)
            #pragma unroll
            for (int j = 0; j < 4; j++) acc[mt][nt][j] = 0.f;

    hmma4_loop<DIN, true>(sbase, m0, n0, tid, g_wi_hi, g_wi_lo, zh, zl, acc);

    int q  = lane >> 2;
    int qq = lane & 3;
    float* C = g_ze + (size_t)b * DCB * TT;
    #pragma unroll
    for (int mt = 0; mt < 2; mt++) {
        int RB = m0 + wm * 32 + mt * 16;
        #pragma unroll
        for (int h = 0; h < 2; h++) {
            int row = RB + h * 8 + q;
            float bb = bias[row];
            float* cw = C + (size_t)row * TT + n0;
            #pragma unroll
            for (int nt = 0; nt < 8; nt++) {
                int c0 = wn * 64 + nt * 8 + qq * 2;
                *(float2*)(cw + c0) = make_float2(acc[mt][nt][h * 2 + 0] + bb,
                                                  acc[mt][nt][h * 2 + 1] + bb);
            }
        }
    }
}

// ---------------- argmin refinement (near-exact fp32) + fused loss ----------
__global__ void k_refine(float* __restrict__ dout)
{
    int warp = threadIdx.x >> 5;
    int lane = threadIdx.x & 31;
    int n = blockIdx.x * 8 + warp;

    const unsigned long long* tm = g_tilemin + (size_t)n * 128;
    unsigned long long best = tm[lane];
    {
        unsigned long long v;
        v = tm[lane + 32]; if (v < best) best = v;
        v = tm[lane + 64]; if (v < best) best = v;
        v = tm[lane + 96]; if (v < best) best = v;
        #pragma unroll
        for (int off = 16; off; off >>= 1) {
            unsigned long long o = __shfl_xor_sync(0xFFFFFFFFu, best, off);
            if (o < best) best = o;
        }
    }
    float dmin = funkey((unsigned)(best >> 32));
    float thresh = dmin + 8e-3f;

    float inv = g_inv[n];
    float rsq = g_rowsq[n];
    float ev[8];
    {
        const __nv_bfloat16* ah = g_a_hi + (size_t)n * DCB + lane * 8;
        const __nv_bfloat16* al = g_a_lo + (size_t)n * DCB + lane * 8;
        #pragma unroll
        for (int j = 0; j < 8; j++)
            ev[j] = __bfloat162float(ah[j]) + __bfloat162float(al[j]);
    }

    const float* distrow = dout + OFF_DIST + (size_t)n * KK;

    float bestd = 3.4e38f;
    int   bestk = KK;
    float bestpart = 0.f;

    for (int ti = 0; ti < 128; ti++) {
        float tmin = funkey((unsigned)(tm[ti] >> 32));
        if (tmin > thresh) continue;
        int k0 = ti * 64;
        float d0 = distrow[k0 + lane];
        float d1 = distrow[k0 + 32 + lane];
        #pragma unroll
        for (int half = 0; half < 2; half++) {
            float dv = (half == 0) ? d0 : d1;
            unsigned mask = __ballot_sync(0xFFFFFFFFu, dv <= thresh);
            while (mask) {
                int j = __ffs(mask) - 1;
                mask &= mask - 1;
                int k = k0 + half * 32 + j;
                const float* cr = g_cbn + (size_t)k * DCB + lane * 8;
                float part = 0.f;
                #pragma unroll
                for (int qv = 0; qv < 8; qv++)
                    part += ev[qv] * cr[qv];
                #pragma unroll
                for (int off = 16; off; off >>= 1)
                    part += __shfl_xor_sync(0xFFFFFFFFu, part, off);
                float de = rsq + g_colsq[k] - 2.f * part;
                if (de < bestd || (de == bestd && k < bestk)) {
                    bestd = de; bestk = k; bestpart = part;
                }
            }
        }
    }

    if (lane == 0) {
        g_idx[n] = bestk;
        dout[OFF_IDX + n] = (float)bestk;
        atomicAdd(&g_counts[bestk], 1);
        float dot_raw = bestpart / (inv * g_cbinv[bestk]);
        g_lossn[n] = g_rowsq_raw[n] + g_cbsq[bestk] - 2.f * dot_raw;
    }
}

// ---------------- z_q_out gather ----------------
__global__ void k_gather(const float* __restrict__ outb, float* __restrict__ dout)
{
    int t  = blockIdx.x * 256 + threadIdx.x;
    int o4 = blockIdx.y * 4;
    int b  = blockIdx.z;
    int idx = g_idx[b * TT + t];
    float4 v = *(const float4*)(g_proj + (size_t)idx * DIN + o4);
    size_t base = OFF_ZQ + (size_t)b * DIN * TT + (size_t)o4 * TT + t;
    dout[base]          = v.x + outb[o4];
    dout[base + TT]     = v.y + outb[o4 + 1];
    dout[base + 2 * TT] = v.z + outb[o4 + 2];
    dout[base + 3 * TT] = v.w + outb[o4 + 3];
}

// ---------------- scalars: losses, perplexity, active ----------------
__global__ void k_final(const float* __restrict__ cs, float* __restrict__ dout)
{
    int tid = threadIdx.x;
    __shared__ float lsum[256];
    {
        int bb = tid >> 4;
        int sl = tid & 15;
        float s = 0.f;
        #pragma unroll 4
        for (int i = 0; i < 64; i++)
            s += g_lossn[bb * TT + sl + i * 16];
        lsum[tid] = s;
    }
    __syncthreads();
    if (tid < BB) {
        float s = 0.f;
        #pragma unroll
        for (int i = 0; i < 16; i++) s += lsum[tid * 16 + i];
        float mean = s / (float)(DCB * TT);
        dout[OFF_COMMIT + tid] = mean * 0.15f;
        dout[OFF_CBL + tid]    = mean;
    }

    float ent = 0.f;
    int   act = 0;
    for (int k = tid; k < KK; k += 256) {
        float cnt = (float)g_counts[k];
        float p   = cnt / (float)NTOK;
        ent += p * logf(p + 1e-10f);
        float ncs = cs[k] * 0.99f + cnt * 0.01f;
        if (ncs > 2.0f) act++;
    }
    __shared__ float se[256];
    __shared__ int   sa[256];
    se[tid] = ent; sa[tid] = act; __syncthreads();
    #pragma unroll
    for (int off = 128; off; off >>= 1) {
        if (tid < off) { se[tid] += se[tid + off]; sa[tid] += sa[tid + off]; }
        __syncthreads();
    }
    if (tid == 0) {
        dout[OFF_PERP] = expf(-se[0]);
        dout[OFF_ACT]  = (float)sa[0];
    }
}

// ---------------- launch (fork-join, fine-grained join events) --------------
extern "C" void kernel_launch(void* const* d_in, const int* in_sizes, int n_in,
                              void* d_out, int out_size)
{
    const float* z     = (const float*)d_in[0];
    const float* in_g  = (const float*)d_in[1];
    const float* in_v  = (const float*)d_in[2];
    const float* in_b  = (const float*)d_in[3];
    const float* out_g = (const float*)d_in[4];
    const float* out_v = (const float*)d_in[5];
    const float* out_b = (const float*)d_in[6];
    const float* cb    = (const float*)d_in[7];
    const float* cs    = (const float*)d_in[8];
    float* dout = (float*)d_out;

    static cudaStream_t s2 = nullptr;
    static cudaEvent_t  evF = nullptr, evW = nullptr, evP = nullptr, evJ = nullptr;
    if (!s2) {
        cudaStreamCreateWithFlags(&s2, cudaStreamNonBlocking);
        cudaEventCreateWithFlags(&evF, cudaEventDisableTiming);
        cudaEventCreateWithFlags(&evW, cudaEventDisableTiming);
        cudaEventCreateWithFlags(&evP, cudaEventDisableTiming);
        cudaEventCreateWithFlags(&evJ, cudaEventDisableTiming);
        cudaFuncSetAttribute(k_dist, cudaFuncAttributeMaxDynamicSharedMemorySize, SMEM_DIST);
        cudaFuncSetAttribute(k_proj, cudaFuncAttributeMaxDynamicSharedMemorySize, SMEM_P4);
        cudaFuncSetAttribute(k_zein, cudaFuncAttributeMaxDynamicSharedMemorySize, SMEM_P4);
    }

    // fork: stream2 does ALL weight prep + proj GEMM
    cudaEventRecord(evF, 0);
    cudaStreamWaitEvent(s2, evF, 0);
    k_prep_win<<<256, 256, 0, s2>>>(in_v, in_g);
    cudaEventRecord(evW, s2);                       // w_in split ready
    k_prep_cbwo<<<1024 + KK, 256, 0, s2>>>(out_v, out_g, cb);
    cudaEventRecord(evP, s2);                       // b_hi/colsq/cbn ready
    {
        dim3 grid(DIN / 128, KK / 128, 1);
        k_proj<<<grid, 256, SMEM_P4, s2>>>();
    }
    cudaEventRecord(evJ, s2);                       // proj ready

    // main chain
    {
        dim3 grid(4, 32, BB);
        k_zsplit<<<grid, 256>>>(z);
    }
    cudaStreamWaitEvent(0, evW, 0);                 // zein needs g_wi_*
    {
        dim3 grid(TT / 128, DCB / 128, BB);
        k_zein<<<grid, 256, SMEM_P4>>>(in_b);
    }
    k_toknorm<<<NTOK / 32, 256>>>();

    cudaStreamWaitEvent(0, evP, 0);                 // dist needs g_b_hi/g_colsq
    {
        dim3 grid(KK / 128, NTOK / 128, 1);
        k_dist<<<grid, 256, SMEM_DIST>>>(dout);
    }
    k_refine<<<NTOK / 8, 256>>>(dout);              // needs g_cbn (covered by evP)

    cudaStreamWaitEvent(0, evJ, 0);                 // gather needs g_proj
    {
        dim3 grid(4, 256, BB);
        k_gather<<<grid, 256>>>(out_b, dout);
    }
    k_final<<<1, 256>>>(cs, dout);
}